// round 3
// baseline (speedup 1.0000x reference)
#include <cuda_runtime.h>
#include <cuda_bf16.h>
#include <math.h>

#define Bb 4
#define Tt 64
#define Cc 256
#define Ff 256
#define Hh 8
#define Dd 32
#define HIDN 512
#define BT (Bb*Tt)            // 256
#define ROWS (BT*Ff)          // 65536
#define C3 (3*Cc)             // 768

// ---------------- scratch (device globals; addresses resolved via cudaGetSymbolAddress) ----
__device__ float g_xs  [ROWS*Cc];    // residual stream (bt,f,c)
__device__ float g_xn  [ROWS*Cc];    // LN1 out, reused as LN2 out
__device__ float g_qkv [ROWS*C3];    // qkv pre-conv; reused as MLP hidden after attention
__device__ float g_att [ROWS*Cc];    // attention out, reused as final pre-transpose
__device__ float g_out1[ROWS*Cc];    // after proj + residual

// ---------------- transpose in: x(b,c,t,f) -> xs(bt,f,c) ----------------
__global__ void k_transpose_in(const float* __restrict__ x, float* __restrict__ xs) {
    __shared__ float tile[32][33];
    int bt = blockIdx.z;
    int b = bt >> 6, t = bt & 63;
    int f0 = blockIdx.x * 32, c0 = blockIdx.y * 32;
    for (int i = threadIdx.y; i < 32; i += 8) {
        int c = c0 + i, f = f0 + threadIdx.x;
        tile[i][threadIdx.x] = x[((size_t)(b*Cc + c)*Tt + t)*Ff + f];
    }
    __syncthreads();
    for (int i = threadIdx.y; i < 32; i += 8) {
        int f = f0 + i, c = c0 + threadIdx.x;
        xs[((size_t)bt*Ff + f)*Cc + c] = tile[threadIdx.x][i];
    }
}

// ---------------- transpose out: fin(bt,f,c) -> out(b,c,t,f) ----------------
__global__ void k_transpose_out(const float* __restrict__ fin, float* __restrict__ out) {
    __shared__ float tile[32][33];
    int bt = blockIdx.z;
    int b = bt >> 6, t = bt & 63;
    int f0 = blockIdx.x * 32, c0 = blockIdx.y * 32;
    for (int i = threadIdx.y; i < 32; i += 8) {
        int f = f0 + i, c = c0 + threadIdx.x;
        tile[i][threadIdx.x] = fin[((size_t)bt*Ff + f)*Cc + c];
    }
    __syncthreads();
    for (int i = threadIdx.y; i < 32; i += 8) {
        int c = c0 + i, f = f0 + threadIdx.x;
        out[((size_t)(b*Cc + c)*Tt + t)*Ff + f] = tile[threadIdx.x][i];
    }
}

// ---------------- layernorm over last dim (256) ----------------
__global__ void k_ln(const float* __restrict__ in, float* __restrict__ outn,
                     const float* __restrict__ g, const float* __restrict__ be) {
    int row = blockIdx.x;
    int tid = threadIdx.x;
    float v = in[(size_t)row*Cc + tid];
    float s = v, q = v*v;
    #pragma unroll
    for (int o = 16; o; o >>= 1) {
        s += __shfl_xor_sync(0xffffffffu, s, o);
        q += __shfl_xor_sync(0xffffffffu, q, o);
    }
    __shared__ float ws[8], wq[8], mv[2];
    int w = tid >> 5, l = tid & 31;
    if (l == 0) { ws[w] = s; wq[w] = q; }
    __syncthreads();
    if (tid == 0) {
        float S = 0.f, Q = 0.f;
        #pragma unroll
        for (int i = 0; i < 8; i++) { S += ws[i]; Q += wq[i]; }
        float mu = S * (1.0f/Cc);
        float var = Q * (1.0f/Cc) - mu*mu;
        mv[0] = mu;
        mv[1] = rsqrtf(var + 1e-5f);
    }
    __syncthreads();
    outn[(size_t)row*Cc + tid] = (v - mv[0]) * mv[1] * g[tid] + be[tid];
}

// ---------------- generic SGEMM: C = A(MxK) @ B(KxN) [+bias][gelu][+res] ----------------
template<int HAS_BIAS, int HAS_RES, int GELU>
__global__ void k_gemm(const float* __restrict__ A, const float* __restrict__ B,
                       float* __restrict__ Co, const float* __restrict__ bias,
                       const float* __restrict__ res, int M, int N, int K) {
    __shared__ float As[16][132];
    __shared__ float Bs[16][64];
    int m0 = blockIdx.y * 128, n0 = blockIdx.x * 64;
    int tid = threadIdx.x;
    int tr = tid >> 4, tc = tid & 15;
    float acc[8][4];
    #pragma unroll
    for (int i = 0; i < 8; i++)
        #pragma unroll
        for (int j = 0; j < 4; j++) acc[i][j] = 0.f;

    for (int k0 = 0; k0 < K; k0 += 16) {
        #pragma unroll
        for (int i = 0; i < 2; i++) {
            int idx = tid + i*256;        // 0..511 float4 slots
            int m = idx >> 2;
            int k4 = (idx & 3) * 4;
            float4 av = *(const float4*)&A[(size_t)(m0+m)*K + k0 + k4];
            As[k4+0][m] = av.x; As[k4+1][m] = av.y;
            As[k4+2][m] = av.z; As[k4+3][m] = av.w;
        }
        {
            int k = tid >> 4, n4 = (tid & 15) * 4;
            *(float4*)&Bs[k][n4] = *(const float4*)&B[(size_t)(k0+k)*N + n0 + n4];
        }
        __syncthreads();
        #pragma unroll
        for (int kk = 0; kk < 16; kk++) {
            float af[8], bf[4];
            #pragma unroll
            for (int i = 0; i < 8; i++) af[i] = As[kk][tr*8 + i];
            #pragma unroll
            for (int j = 0; j < 4; j++) bf[j] = Bs[kk][tc*4 + j];
            #pragma unroll
            for (int i = 0; i < 8; i++)
                #pragma unroll
                for (int j = 0; j < 4; j++) acc[i][j] += af[i]*bf[j];
        }
        __syncthreads();
    }
    #pragma unroll
    for (int i = 0; i < 8; i++) {
        int m = m0 + tr*8 + i;
        #pragma unroll
        for (int j = 0; j < 4; j++) {
            int n = n0 + tc*4 + j;
            float v = acc[i][j];
            if (HAS_BIAS) v += bias[n];
            if (GELU)     v = 0.5f * v * (1.0f + erff(v * 0.7071067811865475f));
            if (HAS_RES)  v += res[(size_t)m*N + n];
            Co[(size_t)m*N + n] = v;
        }
    }
}

// ---------------- attention (depthwise conv3 fused), one block per (bt,h) ----------------
// static smem: KT/VT bf16 [32][258] + PS bf16x2 [8][256]  = 41,216 B  (< 48KB, no opt-in)
__global__ void k_attn(const float* __restrict__ qkvg, const float* __restrict__ dww,
                       const float* __restrict__ temp, float* __restrict__ attn_out) {
    __shared__ __nv_bfloat16  KT[32*258];
    __shared__ __nv_bfloat16  VT[32*258];
    __shared__ __nv_bfloat162 PS[8*256];
    int bt = blockIdx.x, h = blockIdx.y;
    int tid = threadIdx.x, w = tid >> 5, l = tid & 31;
    const float* qkvb = qkvg + (size_t)bt*Ff*C3;
    float tp = temp[h];
    int chq = h*Dd + l, chk = Cc + chq, chv = 2*Cc + chq;
    float wq0 = dww[chq*3], wq1 = dww[chq*3+1], wq2 = dww[chq*3+2];
    float wk0 = dww[chk*3], wk1 = dww[chk*3+1], wk2 = dww[chk*3+2];
    float wv0 = dww[chv*3], wv1 = dww[chv*3+1], wv2 = dww[chv*3+2];

    // conv + l2norm K, conv V, store transposed bf16
    for (int j = w; j < Ff; j += 8) {
        const float* r = qkvb + (size_t)j*C3;
        float kv = wk1*r[chk], vv = wv1*r[chv];
        if (j > 0)    { kv += wk0*r[chk - C3]; vv += wv0*r[chv - C3]; }
        if (j < Ff-1) { kv += wk2*r[chk + C3]; vv += wv2*r[chv + C3]; }
        float ss = kv*kv;
        #pragma unroll
        for (int o = 16; o; o >>= 1) ss += __shfl_xor_sync(0xffffffffu, ss, o);
        float rn = 1.f / fmaxf(sqrtf(ss), 1e-12f);
        KT[l*258 + j] = __float2bfloat16(kv * rn);
        VT[l*258 + j] = __float2bfloat16(vv);
    }
    __syncthreads();

    __nv_bfloat162* ps = PS + w*256;
    for (int it = 0; it < 16; it++) {
        int f0 = it*16 + w*2;                     // this warp: rows f0, f0+1
        const float* r0 = qkvb + (size_t)f0*C3;
        const float* r1 = qkvb + (size_t)(f0+1)*C3;
        float q0 = wq1*r0[chq] + wq2*r0[chq + C3];      // f0 <= 254, right always valid
        if (f0 > 0) q0 += wq0*r0[chq - C3];
        float q1 = wq1*r1[chq] + wq0*r1[chq - C3];      // f0+1 >= 1, left always valid
        if (f0+1 < Ff-1) q1 += wq2*r1[chq + C3];
        float s0 = q0*q0, s1 = q1*q1;
        #pragma unroll
        for (int o = 16; o; o >>= 1) {
            s0 += __shfl_xor_sync(0xffffffffu, s0, o);
            s1 += __shfl_xor_sync(0xffffffffu, s1, o);
        }
        q0 *= 1.f / fmaxf(sqrtf(s0), 1e-12f);
        q1 *= 1.f / fmaxf(sqrtf(s1), 1e-12f);

        float sa[8], sb[8];
        #pragma unroll
        for (int jj = 0; jj < 8; jj++) { sa[jj] = 0.f; sb[jj] = 0.f; }
        #pragma unroll 4
        for (int d = 0; d < 32; d++) {
            float qa = __shfl_sync(0xffffffffu, q0, d);
            float qb = __shfl_sync(0xffffffffu, q1, d);
            #pragma unroll
            for (int jj = 0; jj < 8; jj++) {
                float kv = __bfloat162float(KT[d*258 + l + jj*32]);
                sa[jj] += qa * kv;
                sb[jj] += qb * kv;
            }
        }
        float ma = -1e30f, mb = -1e30f;
        #pragma unroll
        for (int jj = 0; jj < 8; jj++) {
            sa[jj] *= tp; sb[jj] *= tp;
            ma = fmaxf(ma, sa[jj]); mb = fmaxf(mb, sb[jj]);
        }
        #pragma unroll
        for (int o = 16; o; o >>= 1) {
            ma = fmaxf(ma, __shfl_xor_sync(0xffffffffu, ma, o));
            mb = fmaxf(mb, __shfl_xor_sync(0xffffffffu, mb, o));
        }
        float za = 0.f, zb = 0.f;
        #pragma unroll
        for (int jj = 0; jj < 8; jj++) {
            sa[jj] = expf(sa[jj] - ma); za += sa[jj];
            sb[jj] = expf(sb[jj] - mb); zb += sb[jj];
        }
        #pragma unroll
        for (int o = 16; o; o >>= 1) {
            za += __shfl_xor_sync(0xffffffffu, za, o);
            zb += __shfl_xor_sync(0xffffffffu, zb, o);
        }
        float ia = 1.f/za, ib = 1.f/zb;
        #pragma unroll
        for (int jj = 0; jj < 8; jj++)
            ps[l + jj*32] = __floats2bfloat162_rn(sa[jj]*ia, sb[jj]*ib);
        __syncwarp();

        float o0 = 0.f, o1 = 0.f;
        const __nv_bfloat16* vrow = VT + l*258;
        #pragma unroll 8
        for (int j = 0; j < 256; j++) {
            float2 p = __bfloat1622float2(ps[j]);
            float vv = __bfloat162float(vrow[j]);
            o0 += p.x * vv;
            o1 += p.y * vv;
        }
        attn_out[((size_t)bt*Ff + f0  )*Cc + chq] = o0;
        attn_out[((size_t)bt*Ff + f0+1)*Cc + chq] = o1;
        __syncwarp();
    }
}

// ---------------- launch ----------------
extern "C" void kernel_launch(void* const* d_in, const int* in_sizes, int n_in,
                              void* d_out, int out_size) {
    // Resolve input ordering at runtime: signature order vs alphabetical
    // (jax pytree) order, distinguished by the unique size of x (16,777,216).
    const float *x, *n1g, *n1b, *Wqkv, *dww, *Wproj, *temp, *n2g, *n2b, *W1, *b1, *W2, *b2;
    const int X_SIZE = Bb*Cc*Tt*Ff;
    if (n_in >= 13 && in_sizes[0] == X_SIZE) {
        x     = (const float*)d_in[0];
        n1g   = (const float*)d_in[1];
        n1b   = (const float*)d_in[2];
        Wqkv  = (const float*)d_in[3];
        dww   = (const float*)d_in[4];
        Wproj = (const float*)d_in[5];
        temp  = (const float*)d_in[6];
        n2g   = (const float*)d_in[7];
        n2b   = (const float*)d_in[8];
        W1    = (const float*)d_in[9];
        b1    = (const float*)d_in[10];
        W2    = (const float*)d_in[11];
        b2    = (const float*)d_in[12];
    } else {
        W1    = (const float*)d_in[0];
        W2    = (const float*)d_in[1];
        Wproj = (const float*)d_in[2];
        Wqkv  = (const float*)d_in[3];
        b1    = (const float*)d_in[4];
        b2    = (const float*)d_in[5];
        dww   = (const float*)d_in[6];
        n1b   = (const float*)d_in[7];
        n1g   = (const float*)d_in[8];
        n2b   = (const float*)d_in[9];
        n2g   = (const float*)d_in[10];
        temp  = (const float*)d_in[11];
        x     = (const float*)d_in[12];
    }

    // Device-global scratch: MUST resolve real device addresses
    // (passing __device__ symbols from host code yields the host shadow!).
    void *vp;
    float *xs, *xn, *qkv, *att, *out1;
    cudaGetSymbolAddress(&vp, g_xs);   xs   = (float*)vp;
    cudaGetSymbolAddress(&vp, g_xn);   xn   = (float*)vp;
    cudaGetSymbolAddress(&vp, g_qkv);  qkv  = (float*)vp;
    cudaGetSymbolAddress(&vp, g_att);  att  = (float*)vp;
    cudaGetSymbolAddress(&vp, g_out1); out1 = (float*)vp;
    float *mid = qkv;   // qkv dead after attention; reuse as MLP hidden (needs 33.5M <= 50.3M)

    dim3 tb(32, 8);
    // 1. transpose in
    k_transpose_in<<<dim3(Ff/32, Cc/32, BT), tb>>>(x, xs);
    // 2. LN1
    k_ln<<<ROWS, 256>>>(xs, xn, n1g, n1b);
    // 3. QKV gemm
    k_gemm<0,0,0><<<dim3(C3/64, ROWS/128), 256>>>(xn, Wqkv, qkv, nullptr, nullptr, ROWS, C3, Cc);
    // 4. attention (conv fused)
    k_attn<<<dim3(BT, Hh), 256>>>(qkv, dww, temp, att);
    // 5. proj + residual(xs)
    k_gemm<0,1,0><<<dim3(Cc/64, ROWS/128), 256>>>(att, Wproj, out1, nullptr, xs, ROWS, Cc, Cc);
    // 6. LN2
    k_ln<<<ROWS, 256>>>(out1, xn, n2g, n2b);
    // 7. MLP1 + bias + gelu
    k_gemm<1,0,1><<<dim3(HIDN/64, ROWS/128), 256>>>(xn, W1, mid, b1, nullptr, ROWS, HIDN, Cc);
    // 8. MLP2 + bias + residual(out1)
    k_gemm<1,1,0><<<dim3(Cc/64, ROWS/128), 256>>>(mid, W2, att, b2, out1, ROWS, Cc, HIDN);
    // 9. transpose out
    k_transpose_out<<<dim3(Ff/32, Cc/32, BT), tb>>>(att, (float*)d_out);
}

// round 5
// speedup vs baseline: 1.7703x; 1.7703x over previous
#include <cuda_runtime.h>
#include <cuda_bf16.h>
#include <math.h>
#include <stdint.h>

#define Bb 4
#define Tt 64
#define Cc 256
#define Ff 256
#define Hh 8
#define Dd 32
#define HIDN 512
#define BT (Bb*Tt)            // 256
#define ROWS (BT*Ff)          // 65536
#define C3 (3*Cc)             // 768

// ---------------- scratch (device globals; resolved via cudaGetSymbolAddress) ----
__device__ float          g_xs  [ROWS*Cc];    // residual fp32; reused as final out
__device__ float          g_out1[ROWS*Cc];    // after proj + residual
__device__ __nv_bfloat16  g_xn  [ROWS*Cc];    // LN out (bf16)
__device__ __nv_bfloat16  g_att [ROWS*Cc];    // attention out (bf16)
__device__ __nv_bfloat16  g_qkv [ROWS*C3];    // qkv bf16; reused as MLP hidden
__device__ __nv_bfloat16  g_wqkvT [C3*Cc];    // transposed bf16 weights [N][K]
__device__ __nv_bfloat16  g_wprojT[Cc*Cc];
__device__ __nv_bfloat16  g_w1T   [HIDN*Cc];
__device__ __nv_bfloat16  g_w2T   [Cc*HIDN];

__device__ __forceinline__ uint32_t smem_u32(const void* p) {
    uint32_t a;
    asm("{ .reg .u64 t; cvta.to.shared.u64 t, %1; cvt.u32.u64 %0, t; }" : "=r"(a) : "l"(p));
    return a;
}
__device__ __forceinline__ void ldsm4(uint32_t& r0, uint32_t& r1, uint32_t& r2, uint32_t& r3,
                                      uint32_t addr) {
    asm volatile("ldmatrix.sync.aligned.m8n8.x4.shared.b16 {%0,%1,%2,%3}, [%4];"
                 : "=r"(r0), "=r"(r1), "=r"(r2), "=r"(r3) : "r"(addr));
}
__device__ __forceinline__ void mma16816(float* c, const uint32_t* a, const uint32_t* b) {
    asm volatile(
        "mma.sync.aligned.m16n8k16.row.col.f32.bf16.bf16.f32 "
        "{%0,%1,%2,%3}, {%4,%5,%6,%7}, {%8,%9}, {%0,%1,%2,%3};"
        : "+f"(c[0]), "+f"(c[1]), "+f"(c[2]), "+f"(c[3])
        : "r"(a[0]), "r"(a[1]), "r"(a[2]), "r"(a[3]), "r"(b[0]), "r"(b[1]));
}

// ================= transpose in: x(b,c,t,f) -> xs(bt,f,c) =================
__global__ void k_transpose_in(const float* __restrict__ x, float* __restrict__ xs) {
    __shared__ float tile[32][33];
    int bt = blockIdx.z;
    int b = bt >> 6, t = bt & 63;
    int f0 = blockIdx.x * 32, c0 = blockIdx.y * 32;
    for (int i = threadIdx.y; i < 32; i += 8) {
        int c = c0 + i, f = f0 + threadIdx.x;
        tile[i][threadIdx.x] = x[((size_t)(b*Cc + c)*Tt + t)*Ff + f];
    }
    __syncthreads();
    for (int i = threadIdx.y; i < 32; i += 8) {
        int f = f0 + i, c = c0 + threadIdx.x;
        xs[((size_t)bt*Ff + f)*Cc + c] = tile[threadIdx.x][i];
    }
}

// ================= transpose out =================
__global__ void k_transpose_out(const float* __restrict__ fin, float* __restrict__ out) {
    __shared__ float tile[32][33];
    int bt = blockIdx.z;
    int b = bt >> 6, t = bt & 63;
    int f0 = blockIdx.x * 32, c0 = blockIdx.y * 32;
    for (int i = threadIdx.y; i < 32; i += 8) {
        int f = f0 + i, c = c0 + threadIdx.x;
        tile[i][threadIdx.x] = fin[((size_t)bt*Ff + f)*Cc + c];
    }
    __syncthreads();
    for (int i = threadIdx.y; i < 32; i += 8) {
        int c = c0 + i, f = f0 + threadIdx.x;
        out[((size_t)(b*Cc + c)*Tt + t)*Ff + f] = tile[threadIdx.x][i];
    }
}

// ================= layernorm (256) -> bf16 =================
__global__ void k_ln(const float* __restrict__ in, __nv_bfloat16* __restrict__ outn,
                     const float* __restrict__ g, const float* __restrict__ be) {
    int row = blockIdx.x;
    int tid = threadIdx.x;
    float v = in[(size_t)row*Cc + tid];
    float s = v, q = v*v;
    #pragma unroll
    for (int o = 16; o; o >>= 1) {
        s += __shfl_xor_sync(0xffffffffu, s, o);
        q += __shfl_xor_sync(0xffffffffu, q, o);
    }
    __shared__ float ws[8], wq[8], mv[2];
    int w = tid >> 5, l = tid & 31;
    if (l == 0) { ws[w] = s; wq[w] = q; }
    __syncthreads();
    if (tid == 0) {
        float S = 0.f, Q = 0.f;
        #pragma unroll
        for (int i = 0; i < 8; i++) { S += ws[i]; Q += wq[i]; }
        float mu = S * (1.0f/Cc);
        float var = Q * (1.0f/Cc) - mu*mu;
        mv[0] = mu;
        mv[1] = rsqrtf(var + 1e-5f);
    }
    __syncthreads();
    outn[(size_t)row*Cc + tid] = __float2bfloat16((v - mv[0]) * mv[1] * g[tid] + be[tid]);
}

// ================= weight transpose: W(K,N) -> Wt(N,K) bf16 =================
__global__ void k_wt(const float* __restrict__ W, __nv_bfloat16* __restrict__ Wt,
                     int K, int N) {
    int idx = blockIdx.x * 256 + threadIdx.x;
    if (idx >= K*N) return;
    int n = idx / K, k = idx - n*K;
    Wt[idx] = __float2bfloat16(W[(size_t)k*N + n]);
}

// ================= HMMA bf16 GEMM: C = A(M,K) @ Bt(N,K)^T =================
// CTA 128x128, 8 warps (2M x 4N), warp tile 64x32, K chunks of 64, XOR-swizzled smem.
template<int OUT_BF16, int HAS_BIAS, int GELU_F, int HAS_RES>
__global__ __launch_bounds__(256, 2)
void k_mmagemm(const __nv_bfloat16* __restrict__ A, const __nv_bfloat16* __restrict__ Bt,
               void* __restrict__ Co, const float* __restrict__ bias,
               const float* __restrict__ res, int N, int K) {
    __shared__ __nv_bfloat16 As[128*64];
    __shared__ __nv_bfloat16 Bs[128*64];
    int tid = threadIdx.x, wid = tid >> 5, lid = tid & 31;
    int m0 = blockIdx.y * 128, n0 = blockIdx.x * 128;
    int wm = (wid & 1) * 64;        // warp M offset within tile
    int wn = (wid >> 1) * 32;       // warp N offset within tile

    float c[4][4][4];
    #pragma unroll
    for (int mi = 0; mi < 4; mi++)
        #pragma unroll
        for (int ni = 0; ni < 4; ni++)
            #pragma unroll
            for (int j = 0; j < 4; j++) c[mi][ni][j] = 0.f;

    uint32_t sA = smem_u32(As), sB = smem_u32(Bs);

    for (int k0 = 0; k0 < K; k0 += 64) {
        // load A & B 128x64 tiles, swizzled: chunk (row, kb) -> row*64 + (kb^(row&7))*8
        #pragma unroll
        for (int i = 0; i < 4; i++) {
            int u = i*256 + tid;            // 0..1023
            int row = u >> 3, kb = u & 7;
            uint32_t dst = (row*64 + ((kb ^ (row & 7))*8));
            *(uint4*)&As[dst] = *(const uint4*)&A [(size_t)(m0 + row)*K + k0 + kb*8];
            *(uint4*)&Bs[dst] = *(const uint4*)&Bt[(size_t)(n0 + row)*K + k0 + kb*8];
        }
        __syncthreads();

        #pragma unroll
        for (int ks = 0; ks < 4; ks++) {
            uint32_t a[4][4], b[4][2];
            // A frags: 4 m16 tiles
            #pragma unroll
            for (int mi = 0; mi < 4; mi++) {
                int row = wm + mi*16 + (lid & 15);
                int kb  = ks*2 + (lid >> 4);
                uint32_t ad = sA + (row*64 + ((kb ^ (row & 7))*8))*2;
                ldsm4(a[mi][0], a[mi][1], a[mi][2], a[mi][3], ad);
            }
            // B frags: 2 x ldmatrix.x4, each -> two n8 tiles
            #pragma unroll
            for (int nh = 0; nh < 2; nh++) {
                int nrow = wn + nh*16 + (lid & 7) + ((lid >> 4) << 3);
                int kb   = ks*2 + ((lid >> 3) & 1);
                uint32_t bd = sB + (nrow*64 + ((kb ^ (nrow & 7))*8))*2;
                uint32_t r0, r1, r2, r3;
                ldsm4(r0, r1, r2, r3, bd);
                b[nh*2+0][0] = r0; b[nh*2+0][1] = r1;
                b[nh*2+1][0] = r2; b[nh*2+1][1] = r3;
            }
            #pragma unroll
            for (int mi = 0; mi < 4; mi++)
                #pragma unroll
                for (int ni = 0; ni < 4; ni++)
                    mma16816(c[mi][ni], a[mi], b[ni]);
        }
        __syncthreads();
    }

    // epilogue straight from fragments
    int qr = lid >> 2, qc = (lid & 3) * 2;
    #pragma unroll
    for (int mi = 0; mi < 4; mi++) {
        #pragma unroll
        for (int half = 0; half < 2; half++) {
            int m = m0 + wm + mi*16 + qr + half*8;
            #pragma unroll
            for (int ni = 0; ni < 4; ni++) {
                int n = n0 + wn + ni*8 + qc;
                float v0 = c[mi][ni][half*2+0];
                float v1 = c[mi][ni][half*2+1];
                if (HAS_BIAS) { v0 += bias[n]; v1 += bias[n+1]; }
                if (GELU_F) {
                    v0 = 0.5f*v0*(1.0f + erff(v0*0.7071067811865475f));
                    v1 = 0.5f*v1*(1.0f + erff(v1*0.7071067811865475f));
                }
                if (HAS_RES) {
                    float2 r2 = *(const float2*)&res[(size_t)m*N + n];
                    v0 += r2.x; v1 += r2.y;
                }
                if (OUT_BF16) {
                    *(__nv_bfloat162*)((__nv_bfloat16*)Co + (size_t)m*N + n) =
                        __floats2bfloat162_rn(v0, v1);
                } else {
                    *(float2*)((float*)Co + (size_t)m*N + n) = make_float2(v0, v1);
                }
            }
        }
    }
}

// ================= attention (depthwise conv3 fused), block per (bt,h) =================
__global__ void k_attn(const __nv_bfloat16* __restrict__ qkvg, const float* __restrict__ dww,
                       const float* __restrict__ temp, __nv_bfloat16* __restrict__ attn_out) {
    __shared__ __nv_bfloat16  KT[32*258];
    __shared__ __nv_bfloat16  VT[32*258];
    __shared__ __nv_bfloat162 PS[8*256];
    int bt = blockIdx.x, h = blockIdx.y;
    int tid = threadIdx.x, w = tid >> 5, l = tid & 31;
    const __nv_bfloat16* qkvb = qkvg + (size_t)bt*Ff*C3;
    float tp = temp[h];
    int chq = h*Dd + l, chk = Cc + chq, chv = 2*Cc + chq;
    float wq0 = dww[chq*3], wq1 = dww[chq*3+1], wq2 = dww[chq*3+2];
    float wk0 = dww[chk*3], wk1 = dww[chk*3+1], wk2 = dww[chk*3+2];
    float wv0 = dww[chv*3], wv1 = dww[chv*3+1], wv2 = dww[chv*3+2];

    for (int j = w; j < Ff; j += 8) {
        const __nv_bfloat16* r = qkvb + (size_t)j*C3;
        float kv = wk1*__bfloat162float(r[chk]);
        float vv = wv1*__bfloat162float(r[chv]);
        if (j > 0)    { kv += wk0*__bfloat162float(r[chk - C3]); vv += wv0*__bfloat162float(r[chv - C3]); }
        if (j < Ff-1) { kv += wk2*__bfloat162float(r[chk + C3]); vv += wv2*__bfloat162float(r[chv + C3]); }
        float ss = kv*kv;
        #pragma unroll
        for (int o = 16; o; o >>= 1) ss += __shfl_xor_sync(0xffffffffu, ss, o);
        float rn = 1.f / fmaxf(sqrtf(ss), 1e-12f);
        KT[l*258 + j] = __float2bfloat16(kv * rn);
        VT[l*258 + j] = __float2bfloat16(vv);
    }
    __syncthreads();

    __nv_bfloat162* ps = PS + w*256;
    for (int it = 0; it < 16; it++) {
        int f0 = it*16 + w*2;
        const __nv_bfloat16* r0 = qkvb + (size_t)f0*C3;
        const __nv_bfloat16* r1 = qkvb + (size_t)(f0+1)*C3;
        float q0 = wq1*__bfloat162float(r0[chq]) + wq2*__bfloat162float(r0[chq + C3]);
        if (f0 > 0) q0 += wq0*__bfloat162float(r0[chq - C3]);
        float q1 = wq1*__bfloat162float(r1[chq]) + wq0*__bfloat162float(r1[chq - C3]);
        if (f0+1 < Ff-1) q1 += wq2*__bfloat162float(r1[chq + C3]);
        float s0 = q0*q0, s1 = q1*q1;
        #pragma unroll
        for (int o = 16; o; o >>= 1) {
            s0 += __shfl_xor_sync(0xffffffffu, s0, o);
            s1 += __shfl_xor_sync(0xffffffffu, s1, o);
        }
        q0 *= 1.f / fmaxf(sqrtf(s0), 1e-12f);
        q1 *= 1.f / fmaxf(sqrtf(s1), 1e-12f);

        float sa[8], sb[8];
        #pragma unroll
        for (int jj = 0; jj < 8; jj++) { sa[jj] = 0.f; sb[jj] = 0.f; }
        #pragma unroll 4
        for (int d = 0; d < 32; d++) {
            float qa = __shfl_sync(0xffffffffu, q0, d);
            float qb = __shfl_sync(0xffffffffu, q1, d);
            #pragma unroll
            for (int jj = 0; jj < 8; jj++) {
                float kv = __bfloat162float(KT[d*258 + l + jj*32]);
                sa[jj] += qa * kv;
                sb[jj] += qb * kv;
            }
        }
        float ma = -1e30f, mb = -1e30f;
        #pragma unroll
        for (int jj = 0; jj < 8; jj++) {
            sa[jj] *= tp; sb[jj] *= tp;
            ma = fmaxf(ma, sa[jj]); mb = fmaxf(mb, sb[jj]);
        }
        #pragma unroll
        for (int o = 16; o; o >>= 1) {
            ma = fmaxf(ma, __shfl_xor_sync(0xffffffffu, ma, o));
            mb = fmaxf(mb, __shfl_xor_sync(0xffffffffu, mb, o));
        }
        float za = 0.f, zb = 0.f;
        #pragma unroll
        for (int jj = 0; jj < 8; jj++) {
            sa[jj] = expf(sa[jj] - ma); za += sa[jj];
            sb[jj] = expf(sb[jj] - mb); zb += sb[jj];
        }
        #pragma unroll
        for (int o = 16; o; o >>= 1) {
            za += __shfl_xor_sync(0xffffffffu, za, o);
            zb += __shfl_xor_sync(0xffffffffu, zb, o);
        }
        float ia = 1.f/za, ib = 1.f/zb;
        #pragma unroll
        for (int jj = 0; jj < 8; jj++)
            ps[l + jj*32] = __floats2bfloat162_rn(sa[jj]*ia, sb[jj]*ib);
        __syncwarp();

        float o0 = 0.f, o1 = 0.f;
        const __nv_bfloat16* vrow = VT + l*258;
        #pragma unroll 8
        for (int j = 0; j < 256; j++) {
            float2 p = __bfloat1622float2(ps[j]);
            float vv = __bfloat162float(vrow[j]);
            o0 += p.x * vv;
            o1 += p.y * vv;
        }
        attn_out[((size_t)bt*Ff + f0  )*Cc + chq] = __float2bfloat16(o0);
        attn_out[((size_t)bt*Ff + f0+1)*Cc + chq] = __float2bfloat16(o1);
        __syncwarp();
    }
}

// ================= launch =================
extern "C" void kernel_launch(void* const* d_in, const int* in_sizes, int n_in,
                              void* d_out, int out_size) {
    const float *x, *n1g, *n1b, *Wqkv, *dww, *Wproj, *temp, *n2g, *n2b, *W1, *b1, *W2, *b2;
    const int X_SIZE = Bb*Cc*Tt*Ff;
    if (n_in >= 13 && in_sizes[0] == X_SIZE) {
        x     = (const float*)d_in[0];  n1g   = (const float*)d_in[1];
        n1b   = (const float*)d_in[2];  Wqkv  = (const float*)d_in[3];
        dww   = (const float*)d_in[4];  Wproj = (const float*)d_in[5];
        temp  = (const float*)d_in[6];  n2g   = (const float*)d_in[7];
        n2b   = (const float*)d_in[8];  W1    = (const float*)d_in[9];
        b1    = (const float*)d_in[10]; W2    = (const float*)d_in[11];
        b2    = (const float*)d_in[12];
    } else {
        W1    = (const float*)d_in[0];  W2    = (const float*)d_in[1];
        Wproj = (const float*)d_in[2];  Wqkv  = (const float*)d_in[3];
        b1    = (const float*)d_in[4];  b2    = (const float*)d_in[5];
        dww   = (const float*)d_in[6];  n1b   = (const float*)d_in[7];
        n1g   = (const float*)d_in[8];  n2b   = (const float*)d_in[9];
        n2g   = (const float*)d_in[10]; temp  = (const float*)d_in[11];
        x     = (const float*)d_in[12];
    }

    void *vp;
    float *xs, *out1;
    __nv_bfloat16 *xn, *att, *qkv, *wqkvT, *wprojT, *w1T, *w2T;
    cudaGetSymbolAddress(&vp, g_xs);     xs     = (float*)vp;
    cudaGetSymbolAddress(&vp, g_out1);   out1   = (float*)vp;
    cudaGetSymbolAddress(&vp, g_xn);     xn     = (__nv_bfloat16*)vp;
    cudaGetSymbolAddress(&vp, g_att);    att    = (__nv_bfloat16*)vp;
    cudaGetSymbolAddress(&vp, g_qkv);    qkv    = (__nv_bfloat16*)vp;
    cudaGetSymbolAddress(&vp, g_wqkvT);  wqkvT  = (__nv_bfloat16*)vp;
    cudaGetSymbolAddress(&vp, g_wprojT); wprojT = (__nv_bfloat16*)vp;
    cudaGetSymbolAddress(&vp, g_w1T);    w1T    = (__nv_bfloat16*)vp;
    cudaGetSymbolAddress(&vp, g_w2T);    w2T    = (__nv_bfloat16*)vp;
    __nv_bfloat16* hid = qkv;   // qkv dead after attention; reuse for MLP hidden

    // weight transposes (bf16)
    k_wt<<<(Cc*C3 + 255)/256, 256>>>(Wqkv, wqkvT, Cc, C3);
    k_wt<<<(Cc*Cc + 255)/256, 256>>>(Wproj, wprojT, Cc, Cc);
    k_wt<<<(Cc*HIDN + 255)/256, 256>>>(W1, w1T, Cc, HIDN);
    k_wt<<<(HIDN*Cc + 255)/256, 256>>>(W2, w2T, HIDN, Cc);

    dim3 tb(32, 8);
    k_transpose_in<<<dim3(Ff/32, Cc/32, BT), tb>>>(x, xs);
    k_ln<<<ROWS, 256>>>(xs, xn, n1g, n1b);
    k_mmagemm<1,0,0,0><<<dim3(C3/128,   ROWS/128), 256>>>(xn,  wqkvT,  qkv,  nullptr, nullptr, C3,   Cc);
    k_attn<<<dim3(BT, Hh), 256>>>(qkv, dww, temp, att);
    k_mmagemm<0,0,0,1><<<dim3(Cc/128,   ROWS/128), 256>>>(att, wprojT, out1, nullptr, xs,      Cc,   Cc);
    k_ln<<<ROWS, 256>>>(out1, xn, n2g, n2b);
    k_mmagemm<1,1,1,0><<<dim3(HIDN/128, ROWS/128), 256>>>(xn,  w1T,    hid,  b1,      nullptr, HIDN, Cc);
    k_mmagemm<0,1,0,1><<<dim3(Cc/128,   ROWS/128), 256>>>(hid, w2T,    xs,   b2,      out1,    Cc,   HIDN);
    k_transpose_out<<<dim3(Ff/32, Cc/32, BT), tb>>>(xs, (float*)d_out);
}

// round 6
// speedup vs baseline: 1.8688x; 1.0556x over previous
#include <cuda_runtime.h>
#include <cuda_bf16.h>
#include <math.h>
#include <stdint.h>

#define Bb 4
#define Tt 64
#define Cc 256
#define Ff 256
#define Hh 8
#define Dd 32
#define HIDN 512
#define BT (Bb*Tt)            // 256
#define ROWS (BT*Ff)          // 65536
#define C3 (3*Cc)             // 768

// ---------------- scratch (device globals; resolved via cudaGetSymbolAddress) ----
__device__ float          g_xs  [ROWS*Cc];    // residual fp32; reused as final out
__device__ float          g_out1[ROWS*Cc];    // after proj + residual
__device__ __nv_bfloat16  g_xn  [ROWS*Cc];    // LN out (bf16)
__device__ __nv_bfloat16  g_att [ROWS*Cc];    // attention out (bf16)
__device__ __nv_bfloat16  g_qkv [ROWS*C3];    // qkv bf16; reused as MLP hidden
__device__ __nv_bfloat16  g_wqkvT [C3*Cc];    // transposed bf16 weights [N][K]
__device__ __nv_bfloat16  g_wprojT[Cc*Cc];
__device__ __nv_bfloat16  g_w1T   [HIDN*Cc];
__device__ __nv_bfloat16  g_w2T   [Cc*HIDN];

__device__ __forceinline__ uint32_t smem_u32(const void* p) {
    uint32_t a;
    asm("{ .reg .u64 t; cvta.to.shared.u64 t, %1; cvt.u32.u64 %0, t; }" : "=r"(a) : "l"(p));
    return a;
}
__device__ __forceinline__ void ldsm4(uint32_t& r0, uint32_t& r1, uint32_t& r2, uint32_t& r3,
                                      uint32_t addr) {
    asm volatile("ldmatrix.sync.aligned.m8n8.x4.shared.b16 {%0,%1,%2,%3}, [%4];"
                 : "=r"(r0), "=r"(r1), "=r"(r2), "=r"(r3) : "r"(addr));
}
__device__ __forceinline__ void mma16816(float* c, const uint32_t* a, const uint32_t* b) {
    asm volatile(
        "mma.sync.aligned.m16n8k16.row.col.f32.bf16.bf16.f32 "
        "{%0,%1,%2,%3}, {%4,%5,%6,%7}, {%8,%9}, {%0,%1,%2,%3};"
        : "+f"(c[0]), "+f"(c[1]), "+f"(c[2]), "+f"(c[3])
        : "r"(a[0]), "r"(a[1]), "r"(a[2]), "r"(a[3]), "r"(b[0]), "r"(b[1]));
}
__device__ __forceinline__ void cp16(uint32_t sdst, const void* gsrc) {
    asm volatile("cp.async.cg.shared.global [%0], [%1], 16;" :: "r"(sdst), "l"(gsrc));
}
#define CP_COMMIT() asm volatile("cp.async.commit_group;" ::: "memory")
#define CP_WAIT(n)  asm volatile("cp.async.wait_group %0;" :: "n"(n) : "memory")

// ================= transpose in: x(b,c,t,f) -> xs(bt,f,c) =================
__global__ void k_transpose_in(const float* __restrict__ x, float* __restrict__ xs) {
    __shared__ float tile[32][33];
    int bt = blockIdx.z;
    int b = bt >> 6, t = bt & 63;
    int f0 = blockIdx.x * 32, c0 = blockIdx.y * 32;
    for (int i = threadIdx.y; i < 32; i += 8) {
        int c = c0 + i, f = f0 + threadIdx.x;
        tile[i][threadIdx.x] = x[((size_t)(b*Cc + c)*Tt + t)*Ff + f];
    }
    __syncthreads();
    for (int i = threadIdx.y; i < 32; i += 8) {
        int f = f0 + i, c = c0 + threadIdx.x;
        xs[((size_t)bt*Ff + f)*Cc + c] = tile[threadIdx.x][i];
    }
}

// ================= transpose out =================
__global__ void k_transpose_out(const float* __restrict__ fin, float* __restrict__ out) {
    __shared__ float tile[32][33];
    int bt = blockIdx.z;
    int b = bt >> 6, t = bt & 63;
    int f0 = blockIdx.x * 32, c0 = blockIdx.y * 32;
    for (int i = threadIdx.y; i < 32; i += 8) {
        int f = f0 + i, c = c0 + threadIdx.x;
        tile[i][threadIdx.x] = fin[((size_t)bt*Ff + f)*Cc + c];
    }
    __syncthreads();
    for (int i = threadIdx.y; i < 32; i += 8) {
        int c = c0 + i, f = f0 + threadIdx.x;
        out[((size_t)(b*Cc + c)*Tt + t)*Ff + f] = tile[threadIdx.x][i];
    }
}

// ================= layernorm (256) -> bf16 =================
__global__ void k_ln(const float* __restrict__ in, __nv_bfloat16* __restrict__ outn,
                     const float* __restrict__ g, const float* __restrict__ be) {
    int row = blockIdx.x;
    int tid = threadIdx.x;
    float v = in[(size_t)row*Cc + tid];
    float s = v, q = v*v;
    #pragma unroll
    for (int o = 16; o; o >>= 1) {
        s += __shfl_xor_sync(0xffffffffu, s, o);
        q += __shfl_xor_sync(0xffffffffu, q, o);
    }
    __shared__ float ws[8], wq[8], mv[2];
    int w = tid >> 5, l = tid & 31;
    if (l == 0) { ws[w] = s; wq[w] = q; }
    __syncthreads();
    if (tid == 0) {
        float S = 0.f, Q = 0.f;
        #pragma unroll
        for (int i = 0; i < 8; i++) { S += ws[i]; Q += wq[i]; }
        float mu = S * (1.0f/Cc);
        float var = Q * (1.0f/Cc) - mu*mu;
        mv[0] = mu;
        mv[1] = rsqrtf(var + 1e-5f);
    }
    __syncthreads();
    outn[(size_t)row*Cc + tid] = __float2bfloat16((v - mv[0]) * mv[1] * g[tid] + be[tid]);
}

// ================= weight transpose: W(K,N) -> Wt(N,K) bf16 =================
__global__ void k_wt(const float* __restrict__ W, __nv_bfloat16* __restrict__ Wt,
                     int K, int N) {
    int idx = blockIdx.x * 256 + threadIdx.x;
    if (idx >= K*N) return;
    int n = idx / K, k = idx - n*K;
    Wt[idx] = __float2bfloat16(W[(size_t)k*N + n]);
}

// ================= HMMA bf16 GEMM: C = A(M,K) @ Bt(N,K)^T =================
// CTA 128x128, 8 warps (2M x 4N), warp 64x32, K chunks of 64,
// cp.async double-buffered, XOR-swizzled smem.
template<int OUT_BF16, int HAS_BIAS, int GELU_F, int HAS_RES>
__global__ __launch_bounds__(256, 2)
void k_mmagemm(const __nv_bfloat16* __restrict__ A, const __nv_bfloat16* __restrict__ Bt,
               void* __restrict__ Co, const float* __restrict__ bias,
               const float* __restrict__ res, int N, int K) {
    __shared__ __nv_bfloat16 As[2][128*64];
    __shared__ __nv_bfloat16 Bs[2][128*64];
    int tid = threadIdx.x, wid = tid >> 5, lid = tid & 31;
    int m0 = blockIdx.y * 128, n0 = blockIdx.x * 128;
    int wm = (wid & 1) * 64;
    int wn = (wid >> 1) * 32;

    // per-thread fixed load slots: 4 A rows + 4 B rows (16B each)
    int lrow = tid >> 3, lkb = tid & 7;           // row 0..31 (x4 strided), kb 0..7
    uint32_t swoff = (lkb ^ (lrow & 7)) * 8;      // swizzle within row

    float c[4][4][4];
    #pragma unroll
    for (int mi = 0; mi < 4; mi++)
        #pragma unroll
        for (int ni = 0; ni < 4; ni++)
            #pragma unroll
            for (int j = 0; j < 4; j++) c[mi][ni][j] = 0.f;

    uint32_t sA0 = smem_u32(As), sB0 = smem_u32(Bs);
    int nch = K >> 6;

    // prologue: load chunk 0
    {
        const __nv_bfloat16* ga = A  + (size_t)(m0 + lrow)*K + lkb*8;
        const __nv_bfloat16* gb = Bt + (size_t)(n0 + lrow)*K + lkb*8;
        #pragma unroll
        for (int i = 0; i < 4; i++) {
            uint32_t d = ((lrow + i*32)*64 + swoff) * 2;
            cp16(sA0 + d, ga + (size_t)(i*32)*K);
            cp16(sB0 + d, gb + (size_t)(i*32)*K);
        }
        CP_COMMIT();
    }

    for (int cck = 0; cck < nch; cck++) {
        if (cck + 1 < nch) {
            int k0 = (cck + 1) << 6;
            uint32_t ab = ((cck + 1) & 1) ? sA0 + 16384 : sA0;
            uint32_t bb = ((cck + 1) & 1) ? sB0 + 16384 : sB0;
            const __nv_bfloat16* ga = A  + (size_t)(m0 + lrow)*K + k0 + lkb*8;
            const __nv_bfloat16* gb = Bt + (size_t)(n0 + lrow)*K + k0 + lkb*8;
            #pragma unroll
            for (int i = 0; i < 4; i++) {
                uint32_t d = ((lrow + i*32)*64 + swoff) * 2;
                cp16(ab + d, ga + (size_t)(i*32)*K);
                cp16(bb + d, gb + (size_t)(i*32)*K);
            }
            CP_COMMIT();
            CP_WAIT(1);
        } else {
            CP_WAIT(0);
        }
        __syncthreads();

        uint32_t sA = (cck & 1) ? sA0 + 16384 : sA0;
        uint32_t sB = (cck & 1) ? sB0 + 16384 : sB0;
        #pragma unroll
        for (int ks = 0; ks < 4; ks++) {
            uint32_t a[4][4], b[4][2];
            #pragma unroll
            for (int mi = 0; mi < 4; mi++) {
                int row = wm + mi*16 + (lid & 15);
                int kb  = ks*2 + (lid >> 4);
                uint32_t ad = sA + (row*64 + ((kb ^ (row & 7))*8))*2;
                ldsm4(a[mi][0], a[mi][1], a[mi][2], a[mi][3], ad);
            }
            #pragma unroll
            for (int nh = 0; nh < 2; nh++) {
                int nrow = wn + nh*16 + (lid & 7) + ((lid >> 4) << 3);
                int kb   = ks*2 + ((lid >> 3) & 1);
                uint32_t bd = sB + (nrow*64 + ((kb ^ (nrow & 7))*8))*2;
                uint32_t r0, r1, r2, r3;
                ldsm4(r0, r1, r2, r3, bd);
                b[nh*2+0][0] = r0; b[nh*2+0][1] = r1;
                b[nh*2+1][0] = r2; b[nh*2+1][1] = r3;
            }
            #pragma unroll
            for (int mi = 0; mi < 4; mi++)
                #pragma unroll
                for (int ni = 0; ni < 4; ni++)
                    mma16816(c[mi][ni], a[mi], b[ni]);
        }
        __syncthreads();
    }

    // epilogue straight from fragments
    int qr = lid >> 2, qc = (lid & 3) * 2;
    #pragma unroll
    for (int mi = 0; mi < 4; mi++) {
        #pragma unroll
        for (int half = 0; half < 2; half++) {
            int m = m0 + wm + mi*16 + qr + half*8;
            #pragma unroll
            for (int ni = 0; ni < 4; ni++) {
                int n = n0 + wn + ni*8 + qc;
                float v0 = c[mi][ni][half*2+0];
                float v1 = c[mi][ni][half*2+1];
                if (HAS_BIAS) { v0 += bias[n]; v1 += bias[n+1]; }
                if (GELU_F) {
                    v0 = 0.5f*v0*(1.0f + erff(v0*0.7071067811865475f));
                    v1 = 0.5f*v1*(1.0f + erff(v1*0.7071067811865475f));
                }
                if (HAS_RES) {
                    float2 r2 = *(const float2*)&res[(size_t)m*N + n];
                    v0 += r2.x; v1 += r2.y;
                }
                if (OUT_BF16) {
                    *(__nv_bfloat162*)((__nv_bfloat16*)Co + (size_t)m*N + n) =
                        __floats2bfloat162_rn(v0, v1);
                } else {
                    *(float2*)((float*)Co + (size_t)m*N + n) = make_float2(v0, v1);
                }
            }
        }
    }
}

// ================= attention (depthwise conv3 fused), block per (bt,h) =================
__global__ void k_attn(const __nv_bfloat16* __restrict__ qkvg, const float* __restrict__ dww,
                       const float* __restrict__ temp, __nv_bfloat16* __restrict__ attn_out) {
    __shared__ __nv_bfloat16  KT[32*258];
    __shared__ __nv_bfloat16  VT[32*258];
    __shared__ __nv_bfloat162 PS[8*256];
    int bt = blockIdx.x, h = blockIdx.y;
    int tid = threadIdx.x, w = tid >> 5, l = tid & 31;
    const __nv_bfloat16* qkvb = qkvg + (size_t)bt*Ff*C3;
    float tp = temp[h];
    int chq = h*Dd + l, chk = Cc + chq, chv = 2*Cc + chq;
    float wq0 = dww[chq*3], wq1 = dww[chq*3+1], wq2 = dww[chq*3+2];
    float wk0 = dww[chk*3], wk1 = dww[chk*3+1], wk2 = dww[chk*3+2];
    float wv0 = dww[chv*3], wv1 = dww[chv*3+1], wv2 = dww[chv*3+2];

    for (int j = w; j < Ff; j += 8) {
        const __nv_bfloat16* r = qkvb + (size_t)j*C3;
        float kv = wk1*__bfloat162float(r[chk]);
        float vv = wv1*__bfloat162float(r[chv]);
        if (j > 0)    { kv += wk0*__bfloat162float(r[chk - C3]); vv += wv0*__bfloat162float(r[chv - C3]); }
        if (j < Ff-1) { kv += wk2*__bfloat162float(r[chk + C3]); vv += wv2*__bfloat162float(r[chv + C3]); }
        float ss = kv*kv;
        #pragma unroll
        for (int o = 16; o; o >>= 1) ss += __shfl_xor_sync(0xffffffffu, ss, o);
        float rn = 1.f / fmaxf(sqrtf(ss), 1e-12f);
        KT[l*258 + j] = __float2bfloat16(kv * rn);
        VT[l*258 + j] = __float2bfloat16(vv);
    }
    __syncthreads();

    __nv_bfloat162* ps = PS + w*256;
    for (int it = 0; it < 16; it++) {
        int f0 = it*16 + w*2;
        const __nv_bfloat16* r0 = qkvb + (size_t)f0*C3;
        const __nv_bfloat16* r1 = qkvb + (size_t)(f0+1)*C3;
        float q0 = wq1*__bfloat162float(r0[chq]) + wq2*__bfloat162float(r0[chq + C3]);
        if (f0 > 0) q0 += wq0*__bfloat162float(r0[chq - C3]);
        float q1 = wq1*__bfloat162float(r1[chq]) + wq0*__bfloat162float(r1[chq - C3]);
        if (f0+1 < Ff-1) q1 += wq2*__bfloat162float(r1[chq + C3]);
        float s0 = q0*q0, s1 = q1*q1;
        #pragma unroll
        for (int o = 16; o; o >>= 1) {
            s0 += __shfl_xor_sync(0xffffffffu, s0, o);
            s1 += __shfl_xor_sync(0xffffffffu, s1, o);
        }
        q0 *= 1.f / fmaxf(sqrtf(s0), 1e-12f);
        q1 *= 1.f / fmaxf(sqrtf(s1), 1e-12f);

        float sa[8], sb[8];
        #pragma unroll
        for (int jj = 0; jj < 8; jj++) { sa[jj] = 0.f; sb[jj] = 0.f; }
        #pragma unroll 4
        for (int d = 0; d < 32; d++) {
            float qa = __shfl_sync(0xffffffffu, q0, d);
            float qb = __shfl_sync(0xffffffffu, q1, d);
            #pragma unroll
            for (int jj = 0; jj < 8; jj++) {
                float kv = __bfloat162float(KT[d*258 + l + jj*32]);
                sa[jj] += qa * kv;
                sb[jj] += qb * kv;
            }
        }
        float ma = -1e30f, mb = -1e30f;
        #pragma unroll
        for (int jj = 0; jj < 8; jj++) {
            sa[jj] *= tp; sb[jj] *= tp;
            ma = fmaxf(ma, sa[jj]); mb = fmaxf(mb, sb[jj]);
        }
        #pragma unroll
        for (int o = 16; o; o >>= 1) {
            ma = fmaxf(ma, __shfl_xor_sync(0xffffffffu, ma, o));
            mb = fmaxf(mb, __shfl_xor_sync(0xffffffffu, mb, o));
        }
        float za = 0.f, zb = 0.f;
        #pragma unroll
        for (int jj = 0; jj < 8; jj++) {
            sa[jj] = expf(sa[jj] - ma); za += sa[jj];
            sb[jj] = expf(sb[jj] - mb); zb += sb[jj];
        }
        #pragma unroll
        for (int o = 16; o; o >>= 1) {
            za += __shfl_xor_sync(0xffffffffu, za, o);
            zb += __shfl_xor_sync(0xffffffffu, zb, o);
        }
        float ia = 1.f/za, ib = 1.f/zb;
        #pragma unroll
        for (int jj = 0; jj < 8; jj++)
            ps[l + jj*32] = __floats2bfloat162_rn(sa[jj]*ia, sb[jj]*ib);
        __syncwarp();

        float o0 = 0.f, o1 = 0.f;
        const __nv_bfloat16* vrow = VT + l*258;
        #pragma unroll 8
        for (int j = 0; j < 256; j++) {
            float2 p = __bfloat1622float2(ps[j]);
            float vv = __bfloat162float(vrow[j]);
            o0 += p.x * vv;
            o1 += p.y * vv;
        }
        attn_out[((size_t)bt*Ff + f0  )*Cc + chq] = __float2bfloat16(o0);
        attn_out[((size_t)bt*Ff + f0+1)*Cc + chq] = __float2bfloat16(o1);
        __syncwarp();
    }
}

// ================= launch =================
extern "C" void kernel_launch(void* const* d_in, const int* in_sizes, int n_in,
                              void* d_out, int out_size) {
    const float *x, *n1g, *n1b, *Wqkv, *dww, *Wproj, *temp, *n2g, *n2b, *W1, *b1, *W2, *b2;
    const int X_SIZE = Bb*Cc*Tt*Ff;
    if (n_in >= 13 && in_sizes[0] == X_SIZE) {
        x     = (const float*)d_in[0];  n1g   = (const float*)d_in[1];
        n1b   = (const float*)d_in[2];  Wqkv  = (const float*)d_in[3];
        dww   = (const float*)d_in[4];  Wproj = (const float*)d_in[5];
        temp  = (const float*)d_in[6];  n2g   = (const float*)d_in[7];
        n2b   = (const float*)d_in[8];  W1    = (const float*)d_in[9];
        b1    = (const float*)d_in[10]; W2    = (const float*)d_in[11];
        b2    = (const float*)d_in[12];
    } else {
        W1    = (const float*)d_in[0];  W2    = (const float*)d_in[1];
        Wproj = (const float*)d_in[2];  Wqkv  = (const float*)d_in[3];
        b1    = (const float*)d_in[4];  b2    = (const float*)d_in[5];
        dww   = (const float*)d_in[6];  n1b   = (const float*)d_in[7];
        n1g   = (const float*)d_in[8];  n2b   = (const float*)d_in[9];
        n2g   = (const float*)d_in[10]; temp  = (const float*)d_in[11];
        x     = (const float*)d_in[12];
    }

    void *vp;
    float *xs, *out1;
    __nv_bfloat16 *xn, *att, *qkv, *wqkvT, *wprojT, *w1T, *w2T;
    cudaGetSymbolAddress(&vp, g_xs);     xs     = (float*)vp;
    cudaGetSymbolAddress(&vp, g_out1);   out1   = (float*)vp;
    cudaGetSymbolAddress(&vp, g_xn);     xn     = (__nv_bfloat16*)vp;
    cudaGetSymbolAddress(&vp, g_att);    att    = (__nv_bfloat16*)vp;
    cudaGetSymbolAddress(&vp, g_qkv);    qkv    = (__nv_bfloat16*)vp;
    cudaGetSymbolAddress(&vp, g_wqkvT);  wqkvT  = (__nv_bfloat16*)vp;
    cudaGetSymbolAddress(&vp, g_wprojT); wprojT = (__nv_bfloat16*)vp;
    cudaGetSymbolAddress(&vp, g_w1T);    w1T    = (__nv_bfloat16*)vp;
    cudaGetSymbolAddress(&vp, g_w2T);    w2T    = (__nv_bfloat16*)vp;
    __nv_bfloat16* hid = qkv;   // qkv dead after attention; reuse for MLP hidden

    // weight transposes (bf16)
    k_wt<<<(Cc*C3 + 255)/256, 256>>>(Wqkv, wqkvT, Cc, C3);
    k_wt<<<(Cc*Cc + 255)/256, 256>>>(Wproj, wprojT, Cc, Cc);
    k_wt<<<(Cc*HIDN + 255)/256, 256>>>(W1, w1T, Cc, HIDN);
    k_wt<<<(HIDN*Cc + 255)/256, 256>>>(W2, w2T, HIDN, Cc);

    dim3 tb(32, 8);
    k_transpose_in<<<dim3(Ff/32, Cc/32, BT), tb>>>(x, xs);
    k_ln<<<ROWS, 256>>>(xs, xn, n1g, n1b);
    k_mmagemm<1,0,0,0><<<dim3(C3/128,   ROWS/128), 256>>>(xn,  wqkvT,  qkv,  nullptr, nullptr, C3,   Cc);
    k_attn<<<dim3(BT, Hh), 256>>>(qkv, dww, temp, att);
    k_mmagemm<0,0,0,1><<<dim3(Cc/128,   ROWS/128), 256>>>(att, wprojT, out1, nullptr, xs,      Cc,   Cc);
    k_ln<<<ROWS, 256>>>(out1, xn, n2g, n2b);
    k_mmagemm<1,1,1,0><<<dim3(HIDN/128, ROWS/128), 256>>>(xn,  w1T,    hid,  b1,      nullptr, HIDN, Cc);
    k_mmagemm<0,1,0,1><<<dim3(Cc/128,   ROWS/128), 256>>>(hid, w2T,    xs,   b2,      out1,    Cc,   HIDN);
    k_transpose_out<<<dim3(Ff/32, Cc/32, BT), tb>>>(xs, (float*)d_out);
}

// round 7
// speedup vs baseline: 3.2007x; 1.7127x over previous
#include <cuda_runtime.h>
#include <cuda_bf16.h>
#include <math.h>
#include <stdint.h>

#define Bb 4
#define Tt 64
#define Cc 256
#define Ff 256
#define Hh 8
#define Dd 32
#define HIDN 512
#define BT (Bb*Tt)            // 256
#define ROWS (BT*Ff)          // 65536
#define C3 (3*Cc)             // 768

// ---------------- scratch (device globals; resolved via cudaGetSymbolAddress) ----
__device__ float          g_xs  [ROWS*Cc];    // residual fp32; reused as final out
__device__ float          g_out1[ROWS*Cc];    // after proj + residual
__device__ __nv_bfloat16  g_xn  [ROWS*Cc];    // LN out (bf16)
__device__ __nv_bfloat16  g_att [ROWS*Cc];    // attention out (bf16)
__device__ __nv_bfloat16  g_qkv [ROWS*C3];    // qkv bf16; reused as MLP hidden
__device__ __nv_bfloat16  g_wqkvT [C3*Cc];    // transposed bf16 weights [N][K]
__device__ __nv_bfloat16  g_wprojT[Cc*Cc];
__device__ __nv_bfloat16  g_w1T   [HIDN*Cc];
__device__ __nv_bfloat16  g_w2T   [Cc*HIDN];

__device__ __forceinline__ uint32_t smem_u32(const void* p) {
    uint32_t a;
    asm("{ .reg .u64 t; cvta.to.shared.u64 t, %1; cvt.u32.u64 %0, t; }" : "=r"(a) : "l"(p));
    return a;
}
__device__ __forceinline__ void ldsm4(uint32_t& r0, uint32_t& r1, uint32_t& r2, uint32_t& r3,
                                      uint32_t addr) {
    asm volatile("ldmatrix.sync.aligned.m8n8.x4.shared.b16 {%0,%1,%2,%3}, [%4];"
                 : "=r"(r0), "=r"(r1), "=r"(r2), "=r"(r3) : "r"(addr));
}
__device__ __forceinline__ void ldsm4t(uint32_t& r0, uint32_t& r1, uint32_t& r2, uint32_t& r3,
                                       uint32_t addr) {
    asm volatile("ldmatrix.sync.aligned.m8n8.x4.trans.shared.b16 {%0,%1,%2,%3}, [%4];"
                 : "=r"(r0), "=r"(r1), "=r"(r2), "=r"(r3) : "r"(addr));
}
__device__ __forceinline__ void mma16816(float* c, const uint32_t* a, const uint32_t* b) {
    asm volatile(
        "mma.sync.aligned.m16n8k16.row.col.f32.bf16.bf16.f32 "
        "{%0,%1,%2,%3}, {%4,%5,%6,%7}, {%8,%9}, {%0,%1,%2,%3};"
        : "+f"(c[0]), "+f"(c[1]), "+f"(c[2]), "+f"(c[3])
        : "r"(a[0]), "r"(a[1]), "r"(a[2]), "r"(a[3]), "r"(b[0]), "r"(b[1]));
}
__device__ __forceinline__ void cp16(uint32_t sdst, const void* gsrc) {
    asm volatile("cp.async.cg.shared.global [%0], [%1], 16;" :: "r"(sdst), "l"(gsrc));
}
#define CP_COMMIT() asm volatile("cp.async.commit_group;" ::: "memory")
#define CP_WAIT(n)  asm volatile("cp.async.wait_group %0;" :: "n"(n) : "memory")

// ================= transpose in: x(b,c,t,f) -> xs(bt,f,c) =================
__global__ void k_transpose_in(const float* __restrict__ x, float* __restrict__ xs) {
    __shared__ float tile[32][33];
    int bt = blockIdx.z;
    int b = bt >> 6, t = bt & 63;
    int f0 = blockIdx.x * 32, c0 = blockIdx.y * 32;
    for (int i = threadIdx.y; i < 32; i += 8) {
        int c = c0 + i, f = f0 + threadIdx.x;
        tile[i][threadIdx.x] = x[((size_t)(b*Cc + c)*Tt + t)*Ff + f];
    }
    __syncthreads();
    for (int i = threadIdx.y; i < 32; i += 8) {
        int f = f0 + i, c = c0 + threadIdx.x;
        xs[((size_t)bt*Ff + f)*Cc + c] = tile[threadIdx.x][i];
    }
}

// ================= transpose out =================
__global__ void k_transpose_out(const float* __restrict__ fin, float* __restrict__ out) {
    __shared__ float tile[32][33];
    int bt = blockIdx.z;
    int b = bt >> 6, t = bt & 63;
    int f0 = blockIdx.x * 32, c0 = blockIdx.y * 32;
    for (int i = threadIdx.y; i < 32; i += 8) {
        int f = f0 + i, c = c0 + threadIdx.x;
        tile[i][threadIdx.x] = fin[((size_t)bt*Ff + f)*Cc + c];
    }
    __syncthreads();
    for (int i = threadIdx.y; i < 32; i += 8) {
        int c = c0 + i, f = f0 + threadIdx.x;
        out[((size_t)(b*Cc + c)*Tt + t)*Ff + f] = tile[threadIdx.x][i];
    }
}

// ================= layernorm (256) -> bf16 =================
__global__ void k_ln(const float* __restrict__ in, __nv_bfloat16* __restrict__ outn,
                     const float* __restrict__ g, const float* __restrict__ be) {
    int row = blockIdx.x;
    int tid = threadIdx.x;
    float v = in[(size_t)row*Cc + tid];
    float s = v, q = v*v;
    #pragma unroll
    for (int o = 16; o; o >>= 1) {
        s += __shfl_xor_sync(0xffffffffu, s, o);
        q += __shfl_xor_sync(0xffffffffu, q, o);
    }
    __shared__ float ws[8], wq[8], mv[2];
    int w = tid >> 5, l = tid & 31;
    if (l == 0) { ws[w] = s; wq[w] = q; }
    __syncthreads();
    if (tid == 0) {
        float S = 0.f, Q = 0.f;
        #pragma unroll
        for (int i = 0; i < 8; i++) { S += ws[i]; Q += wq[i]; }
        float mu = S * (1.0f/Cc);
        float var = Q * (1.0f/Cc) - mu*mu;
        mv[0] = mu;
        mv[1] = rsqrtf(var + 1e-5f);
    }
    __syncthreads();
    outn[(size_t)row*Cc + tid] = __float2bfloat16((v - mv[0]) * mv[1] * g[tid] + be[tid]);
}

// ================= weight transpose: W(K,N) -> Wt(N,K) bf16 =================
__global__ void k_wt(const float* __restrict__ W, __nv_bfloat16* __restrict__ Wt,
                     int K, int N) {
    int idx = blockIdx.x * 256 + threadIdx.x;
    if (idx >= K*N) return;
    int n = idx / K, k = idx - n*K;
    Wt[idx] = __float2bfloat16(W[(size_t)k*N + n]);
}

// ================= HMMA bf16 GEMM: C = A(M,K) @ Bt(N,K)^T =================
template<int OUT_BF16, int HAS_BIAS, int GELU_F, int HAS_RES>
__global__ __launch_bounds__(256, 2)
void k_mmagemm(const __nv_bfloat16* __restrict__ A, const __nv_bfloat16* __restrict__ Bt,
               void* __restrict__ Co, const float* __restrict__ bias,
               const float* __restrict__ res, int N, int K) {
    __shared__ __nv_bfloat16 As[2][128*64];
    __shared__ __nv_bfloat16 Bs[2][128*64];
    int tid = threadIdx.x, wid = tid >> 5, lid = tid & 31;
    int m0 = blockIdx.y * 128, n0 = blockIdx.x * 128;
    int wm = (wid & 1) * 64;
    int wn = (wid >> 1) * 32;

    int lrow = tid >> 3, lkb = tid & 7;
    uint32_t swoff = (lkb ^ (lrow & 7)) * 8;

    float c[4][4][4];
    #pragma unroll
    for (int mi = 0; mi < 4; mi++)
        #pragma unroll
        for (int ni = 0; ni < 4; ni++)
            #pragma unroll
            for (int j = 0; j < 4; j++) c[mi][ni][j] = 0.f;

    uint32_t sA0 = smem_u32(As), sB0 = smem_u32(Bs);
    int nch = K >> 6;

    {
        const __nv_bfloat16* ga = A  + (size_t)(m0 + lrow)*K + lkb*8;
        const __nv_bfloat16* gb = Bt + (size_t)(n0 + lrow)*K + lkb*8;
        #pragma unroll
        for (int i = 0; i < 4; i++) {
            uint32_t d = ((lrow + i*32)*64 + swoff) * 2;
            cp16(sA0 + d, ga + (size_t)(i*32)*K);
            cp16(sB0 + d, gb + (size_t)(i*32)*K);
        }
        CP_COMMIT();
    }

    for (int cck = 0; cck < nch; cck++) {
        if (cck + 1 < nch) {
            int k0 = (cck + 1) << 6;
            uint32_t ab = ((cck + 1) & 1) ? sA0 + 16384 : sA0;
            uint32_t bb = ((cck + 1) & 1) ? sB0 + 16384 : sB0;
            const __nv_bfloat16* ga = A  + (size_t)(m0 + lrow)*K + k0 + lkb*8;
            const __nv_bfloat16* gb = Bt + (size_t)(n0 + lrow)*K + k0 + lkb*8;
            #pragma unroll
            for (int i = 0; i < 4; i++) {
                uint32_t d = ((lrow + i*32)*64 + swoff) * 2;
                cp16(ab + d, ga + (size_t)(i*32)*K);
                cp16(bb + d, gb + (size_t)(i*32)*K);
            }
            CP_COMMIT();
            CP_WAIT(1);
        } else {
            CP_WAIT(0);
        }
        __syncthreads();

        uint32_t sA = (cck & 1) ? sA0 + 16384 : sA0;
        uint32_t sB = (cck & 1) ? sB0 + 16384 : sB0;
        #pragma unroll
        for (int ks = 0; ks < 4; ks++) {
            uint32_t a[4][4], b[4][2];
            #pragma unroll
            for (int mi = 0; mi < 4; mi++) {
                int row = wm + mi*16 + (lid & 15);
                int kb  = ks*2 + (lid >> 4);
                uint32_t ad = sA + (row*64 + ((kb ^ (row & 7))*8))*2;
                ldsm4(a[mi][0], a[mi][1], a[mi][2], a[mi][3], ad);
            }
            #pragma unroll
            for (int nh = 0; nh < 2; nh++) {
                int nrow = wn + nh*16 + (lid & 7) + ((lid >> 4) << 3);
                int kb   = ks*2 + ((lid >> 3) & 1);
                uint32_t bd = sB + (nrow*64 + ((kb ^ (nrow & 7))*8))*2;
                uint32_t r0, r1, r2, r3;
                ldsm4(r0, r1, r2, r3, bd);
                b[nh*2+0][0] = r0; b[nh*2+0][1] = r1;
                b[nh*2+1][0] = r2; b[nh*2+1][1] = r3;
            }
            #pragma unroll
            for (int mi = 0; mi < 4; mi++)
                #pragma unroll
                for (int ni = 0; ni < 4; ni++)
                    mma16816(c[mi][ni], a[mi], b[ni]);
        }
        __syncthreads();
    }

    int qr = lid >> 2, qc = (lid & 3) * 2;
    #pragma unroll
    for (int mi = 0; mi < 4; mi++) {
        #pragma unroll
        for (int half = 0; half < 2; half++) {
            int m = m0 + wm + mi*16 + qr + half*8;
            #pragma unroll
            for (int ni = 0; ni < 4; ni++) {
                int n = n0 + wn + ni*8 + qc;
                float v0 = c[mi][ni][half*2+0];
                float v1 = c[mi][ni][half*2+1];
                if (HAS_BIAS) { v0 += bias[n]; v1 += bias[n+1]; }
                if (GELU_F) {
                    v0 = 0.5f*v0*(1.0f + erff(v0*0.7071067811865475f));
                    v1 = 0.5f*v1*(1.0f + erff(v1*0.7071067811865475f));
                }
                if (HAS_RES) {
                    float2 r2 = *(const float2*)&res[(size_t)m*N + n];
                    v0 += r2.x; v1 += r2.y;
                }
                if (OUT_BF16) {
                    *(__nv_bfloat162*)((__nv_bfloat16*)Co + (size_t)m*N + n) =
                        __floats2bfloat162_rn(v0, v1);
                } else {
                    *(float2*)((float*)Co + (size_t)m*N + n) = make_float2(v0, v1);
                }
            }
        }
    }
}

// ================= attention via HMMA (conv3 fused), block per (bt,h) =================
// smem: Q/K/V [256 rows][32 bf16], row stride 40 elems (80 B -> ldmatrix conflict-free)
#define ATTN_SMEM (3*256*40*2)   // 61440 B (dynamic, needs opt-in)

__global__ __launch_bounds__(256, 1)
void k_attn(const __nv_bfloat16* __restrict__ qkvg, const float* __restrict__ dww,
            const float* __restrict__ temp, __nv_bfloat16* __restrict__ attn_out) {
    extern __shared__ __nv_bfloat16 smA[];
    __nv_bfloat16* Qs = smA;
    __nv_bfloat16* Ks = smA + 256*40;
    __nv_bfloat16* Vs = smA + 2*256*40;
    int bt = blockIdx.x, h = blockIdx.y;
    int tid = threadIdx.x, w = tid >> 5, l = tid & 31;
    const __nv_bfloat16* qkvb = qkvg + (size_t)bt*Ff*C3;
    float tp = temp[h];
    int chq = h*Dd + l, chk = Cc + chq, chv = 2*Cc + chq;
    float wq0 = dww[chq*3], wq1 = dww[chq*3+1], wq2 = dww[chq*3+2];
    float wk0 = dww[chk*3], wk1 = dww[chk*3+1], wk2 = dww[chk*3+2];
    float wv0 = dww[chv*3], wv1 = dww[chv*3+1], wv2 = dww[chv*3+2];

    // prologue: conv3 + l2norm(Q,K), conv3(V) -> smem (lane = d)
    for (int i = 0; i < 32; i++) {
        int j = w*32 + i;
        const __nv_bfloat16* r = qkvb + (size_t)j*C3;
        float qv = wq1*__bfloat162float(r[chq]);
        float kv = wk1*__bfloat162float(r[chk]);
        float vv = wv1*__bfloat162float(r[chv]);
        if (j > 0) {
            qv += wq0*__bfloat162float(r[chq - C3]);
            kv += wk0*__bfloat162float(r[chk - C3]);
            vv += wv0*__bfloat162float(r[chv - C3]);
        }
        if (j < Ff-1) {
            qv += wq2*__bfloat162float(r[chq + C3]);
            kv += wk2*__bfloat162float(r[chk + C3]);
            vv += wv2*__bfloat162float(r[chv + C3]);
        }
        float sq = qv*qv, sk = kv*kv;
        #pragma unroll
        for (int o = 16; o; o >>= 1) {
            sq += __shfl_xor_sync(0xffffffffu, sq, o);
            sk += __shfl_xor_sync(0xffffffffu, sk, o);
        }
        qv *= 1.f / fmaxf(sqrtf(sq), 1e-12f);
        kv *= 1.f / fmaxf(sqrtf(sk), 1e-12f);
        Qs[j*40 + l] = __float2bfloat16(qv);
        Ks[j*40 + l] = __float2bfloat16(kv);
        Vs[j*40 + l] = __float2bfloat16(vv);
    }
    __syncthreads();

    uint32_t sQ = smem_u32(Qs), sK = smem_u32(Ks), sV = smem_u32(Vs);
    int lid = l;
    int qr = lid >> 2;

    #pragma unroll
    for (int pass = 0; pass < 2; pass++) {
        int m0 = w*32 + pass*16;          // this warp's m16 query tile

        // A frags of Q (k=32 -> 2 k16 steps)
        uint32_t a[2][4];
        #pragma unroll
        for (int ks = 0; ks < 2; ks++) {
            int row = m0 + (lid & 15);
            int kb  = ks*2 + (lid >> 4);
            ldsm4(a[ks][0], a[ks][1], a[ks][2], a[ks][3], sQ + (row*40 + kb*8)*2);
        }

        // S = Q K^T : 32 n8 tiles x 4 regs
        float s[32][4];
        #pragma unroll
        for (int nt = 0; nt < 32; nt++)
            #pragma unroll
            for (int j = 0; j < 4; j++) s[nt][j] = 0.f;
        #pragma unroll
        for (int ng = 0; ng < 16; ng++) {
            #pragma unroll
            for (int ks = 0; ks < 2; ks++) {
                int nrow = ng*16 + (lid & 7) + ((lid >> 4) << 3);
                int kb   = ks*2 + ((lid >> 3) & 1);
                uint32_t r0, r1, r2, r3;
                ldsm4(r0, r1, r2, r3, sK + (nrow*40 + kb*8)*2);
                uint32_t b0[2] = {r0, r1}, b1[2] = {r2, r3};
                mma16816(s[ng*2],   a[ks], b0);
                mma16816(s[ng*2+1], a[ks], b1);
            }
        }

        // softmax (rows qr and qr+8 of this m16 tile)
        float mlo = -1e30f, mhi = -1e30f;
        #pragma unroll
        for (int nt = 0; nt < 32; nt++) {
            #pragma unroll
            for (int j = 0; j < 4; j++) s[nt][j] *= tp;
            mlo = fmaxf(mlo, fmaxf(s[nt][0], s[nt][1]));
            mhi = fmaxf(mhi, fmaxf(s[nt][2], s[nt][3]));
        }
        #pragma unroll
        for (int o = 1; o <= 2; o <<= 1) {
            mlo = fmaxf(mlo, __shfl_xor_sync(0xffffffffu, mlo, o));
            mhi = fmaxf(mhi, __shfl_xor_sync(0xffffffffu, mhi, o));
        }
        float zlo = 0.f, zhi = 0.f;
        #pragma unroll
        for (int nt = 0; nt < 32; nt++) {
            s[nt][0] = __expf(s[nt][0] - mlo);
            s[nt][1] = __expf(s[nt][1] - mlo);
            s[nt][2] = __expf(s[nt][2] - mhi);
            s[nt][3] = __expf(s[nt][3] - mhi);
            zlo += s[nt][0] + s[nt][1];
            zhi += s[nt][2] + s[nt][3];
        }
        #pragma unroll
        for (int o = 1; o <= 2; o <<= 1) {
            zlo += __shfl_xor_sync(0xffffffffu, zlo, o);
            zhi += __shfl_xor_sync(0xffffffffu, zhi, o);
        }

        // O = P V : 4 n8 tiles (d=32), k = 256 keys = 16 k16 steps
        float ov[4][4];
        #pragma unroll
        for (int nt = 0; nt < 4; nt++)
            #pragma unroll
            for (int j = 0; j < 4; j++) ov[nt][j] = 0.f;
        #pragma unroll
        for (int kk = 0; kk < 16; kk++) {
            uint32_t pa[4];
            {
                __nv_bfloat162 t0 = __floats2bfloat162_rn(s[2*kk][0],   s[2*kk][1]);
                __nv_bfloat162 t1 = __floats2bfloat162_rn(s[2*kk][2],   s[2*kk][3]);
                __nv_bfloat162 t2 = __floats2bfloat162_rn(s[2*kk+1][0], s[2*kk+1][1]);
                __nv_bfloat162 t3 = __floats2bfloat162_rn(s[2*kk+1][2], s[2*kk+1][3]);
                pa[0] = *(uint32_t*)&t0; pa[1] = *(uint32_t*)&t1;
                pa[2] = *(uint32_t*)&t2; pa[3] = *(uint32_t*)&t3;
            }
            int vrow = kk*16 + (lid & 15);
            #pragma unroll
            for (int half = 0; half < 2; half++) {
                uint32_t r0, r1, r2, r3;
                ldsm4t(r0, r1, r2, r3, sV + (vrow*40)*2 + (lid >> 4)*16 + half*32);
                uint32_t b0[2] = {r0, r1}, b1[2] = {r2, r3};
                mma16816(ov[half*2+0], pa, b0);
                mma16816(ov[half*2+1], pa, b1);
            }
        }

        // normalize + store
        float ilo = 1.f/zlo, ihi = 1.f/zhi;
        #pragma unroll
        for (int nt = 0; nt < 4; nt++) {
            int col = h*Dd + nt*8 + (lid & 3)*2;
            int flo = m0 + qr, fhi = m0 + qr + 8;
            *(__nv_bfloat162*)&attn_out[((size_t)bt*Ff + flo)*Cc + col] =
                __floats2bfloat162_rn(ov[nt][0]*ilo, ov[nt][1]*ilo);
            *(__nv_bfloat162*)&attn_out[((size_t)bt*Ff + fhi)*Cc + col] =
                __floats2bfloat162_rn(ov[nt][2]*ihi, ov[nt][3]*ihi);
        }
    }
}

// ================= launch =================
extern "C" void kernel_launch(void* const* d_in, const int* in_sizes, int n_in,
                              void* d_out, int out_size) {
    const float *x, *n1g, *n1b, *Wqkv, *dww, *Wproj, *temp, *n2g, *n2b, *W1, *b1, *W2, *b2;
    const int X_SIZE = Bb*Cc*Tt*Ff;
    if (n_in >= 13 && in_sizes[0] == X_SIZE) {
        x     = (const float*)d_in[0];  n1g   = (const float*)d_in[1];
        n1b   = (const float*)d_in[2];  Wqkv  = (const float*)d_in[3];
        dww   = (const float*)d_in[4];  Wproj = (const float*)d_in[5];
        temp  = (const float*)d_in[6];  n2g   = (const float*)d_in[7];
        n2b   = (const float*)d_in[8];  W1    = (const float*)d_in[9];
        b1    = (const float*)d_in[10]; W2    = (const float*)d_in[11];
        b2    = (const float*)d_in[12];
    } else {
        W1    = (const float*)d_in[0];  W2    = (const float*)d_in[1];
        Wproj = (const float*)d_in[2];  Wqkv  = (const float*)d_in[3];
        b1    = (const float*)d_in[4];  b2    = (const float*)d_in[5];
        dww   = (const float*)d_in[6];  n1b   = (const float*)d_in[7];
        n1g   = (const float*)d_in[8];  n2b   = (const float*)d_in[9];
        n2g   = (const float*)d_in[10]; temp  = (const float*)d_in[11];
        x     = (const float*)d_in[12];
    }

    void *vp;
    float *xs, *out1;
    __nv_bfloat16 *xn, *att, *qkv, *wqkvT, *wprojT, *w1T, *w2T;
    cudaGetSymbolAddress(&vp, g_xs);     xs     = (float*)vp;
    cudaGetSymbolAddress(&vp, g_out1);   out1   = (float*)vp;
    cudaGetSymbolAddress(&vp, g_xn);     xn     = (__nv_bfloat16*)vp;
    cudaGetSymbolAddress(&vp, g_att);    att    = (__nv_bfloat16*)vp;
    cudaGetSymbolAddress(&vp, g_qkv);    qkv    = (__nv_bfloat16*)vp;
    cudaGetSymbolAddress(&vp, g_wqkvT);  wqkvT  = (__nv_bfloat16*)vp;
    cudaGetSymbolAddress(&vp, g_wprojT); wprojT = (__nv_bfloat16*)vp;
    cudaGetSymbolAddress(&vp, g_w1T);    w1T    = (__nv_bfloat16*)vp;
    cudaGetSymbolAddress(&vp, g_w2T);    w2T    = (__nv_bfloat16*)vp;
    __nv_bfloat16* hid = qkv;   // qkv dead after attention; reuse for MLP hidden

    cudaFuncSetAttribute(k_attn, cudaFuncAttributeMaxDynamicSharedMemorySize, ATTN_SMEM);

    // weight transposes (bf16)
    k_wt<<<(Cc*C3 + 255)/256, 256>>>(Wqkv, wqkvT, Cc, C3);
    k_wt<<<(Cc*Cc + 255)/256, 256>>>(Wproj, wprojT, Cc, Cc);
    k_wt<<<(Cc*HIDN + 255)/256, 256>>>(W1, w1T, Cc, HIDN);
    k_wt<<<(HIDN*Cc + 255)/256, 256>>>(W2, w2T, HIDN, Cc);

    dim3 tb(32, 8);
    k_transpose_in<<<dim3(Ff/32, Cc/32, BT), tb>>>(x, xs);
    k_ln<<<ROWS, 256>>>(xs, xn, n1g, n1b);
    k_mmagemm<1,0,0,0><<<dim3(C3/128,   ROWS/128), 256>>>(xn,  wqkvT,  qkv,  nullptr, nullptr, C3,   Cc);
    k_attn<<<dim3(BT, Hh), 256, ATTN_SMEM>>>(qkv, dww, temp, att);
    k_mmagemm<0,0,0,1><<<dim3(Cc/128,   ROWS/128), 256>>>(att, wprojT, out1, nullptr, xs,      Cc,   Cc);
    k_ln<<<ROWS, 256>>>(out1, xn, n2g, n2b);
    k_mmagemm<1,1,1,0><<<dim3(HIDN/128, ROWS/128), 256>>>(xn,  w1T,    hid,  b1,      nullptr, HIDN, Cc);
    k_mmagemm<0,1,0,1><<<dim3(Cc/128,   ROWS/128), 256>>>(hid, w2T,    xs,   b2,      out1,    Cc,   HIDN);
    k_transpose_out<<<dim3(Ff/32, Cc/32, BT), tb>>>(xs, (float*)d_out);
}

// round 9
// speedup vs baseline: 3.8000x; 1.1873x over previous
#include <cuda_runtime.h>
#include <cuda_bf16.h>
#include <math.h>
#include <stdint.h>

#define Bb 4
#define Tt 64
#define Cc 256
#define Ff 256
#define Hh 8
#define Dd 32
#define HIDN 512
#define BT (Bb*Tt)            // 256
#define ROWS (BT*Ff)          // 65536
#define C3 (3*Cc)             // 768

// ---------------- scratch (device globals; resolved via cudaGetSymbolAddress) ----
__device__ float          g_xs  [ROWS*Cc];    // residual fp32 (raw transposed x)
__device__ float          g_out1[ROWS*Cc];    // after proj + residual
__device__ __nv_bfloat16  g_xn  [ROWS*Cc];    // LN out (bf16)
__device__ __nv_bfloat16  g_att [ROWS*Cc];    // attention out (bf16)
__device__ __nv_bfloat16  g_qkv [ROWS*C3];    // qkv bf16; reused as MLP hidden
__device__ __nv_bfloat16  g_wqkvT [C3*Cc];    // transposed bf16 weights [N][K]
__device__ __nv_bfloat16  g_wprojT[Cc*Cc];
__device__ __nv_bfloat16  g_w1T   [HIDN*Cc];
__device__ __nv_bfloat16  g_w2T   [Cc*HIDN];

__device__ __forceinline__ uint32_t smem_u32(const void* p) {
    uint32_t a;
    asm("{ .reg .u64 t; cvta.to.shared.u64 t, %1; cvt.u32.u64 %0, t; }" : "=r"(a) : "l"(p));
    return a;
}
__device__ __forceinline__ void ldsm4(uint32_t& r0, uint32_t& r1, uint32_t& r2, uint32_t& r3,
                                      uint32_t addr) {
    asm volatile("ldmatrix.sync.aligned.m8n8.x4.shared.b16 {%0,%1,%2,%3}, [%4];"
                 : "=r"(r0), "=r"(r1), "=r"(r2), "=r"(r3) : "r"(addr));
}
__device__ __forceinline__ void ldsm4t(uint32_t& r0, uint32_t& r1, uint32_t& r2, uint32_t& r3,
                                       uint32_t addr) {
    asm volatile("ldmatrix.sync.aligned.m8n8.x4.trans.shared.b16 {%0,%1,%2,%3}, [%4];"
                 : "=r"(r0), "=r"(r1), "=r"(r2), "=r"(r3) : "r"(addr));
}
__device__ __forceinline__ void mma16816(float* c, const uint32_t* a, const uint32_t* b) {
    asm volatile(
        "mma.sync.aligned.m16n8k16.row.col.f32.bf16.bf16.f32 "
        "{%0,%1,%2,%3}, {%4,%5,%6,%7}, {%8,%9}, {%0,%1,%2,%3};"
        : "+f"(c[0]), "+f"(c[1]), "+f"(c[2]), "+f"(c[3])
        : "r"(a[0]), "r"(a[1]), "r"(a[2]), "r"(a[3]), "r"(b[0]), "r"(b[1]));
}
__device__ __forceinline__ void cp16(uint32_t sdst, const void* gsrc) {
    asm volatile("cp.async.cg.shared.global [%0], [%1], 16;" :: "r"(sdst), "l"(gsrc));
}
#define CP_COMMIT() asm volatile("cp.async.commit_group;" ::: "memory")
#define CP_WAIT(n)  asm volatile("cp.async.wait_group %0;" :: "n"(n) : "memory")

// ================= fused input: transpose x(b,c,t,f)->(bt,f,c) + LN1 =================
// block: (f-tile of 32, one bt). smem tile [c=256][f=32] padded.
__global__ __launch_bounds__(256)
void k_in(const float* __restrict__ x, float* __restrict__ xs,
          __nv_bfloat16* __restrict__ xn,
          const float* __restrict__ g, const float* __restrict__ be) {
    __shared__ float tile[256][33];
    __shared__ float ps_[8][32], pq_[8][32];
    __shared__ float smu[32], srs[32];
    int bt = blockIdx.y, f0 = blockIdx.x * 32;
    int b = bt >> 6, t = bt & 63;
    int tid = threadIdx.x;
    int f = tid & 31, s = tid >> 5;

    const float* xb = x + ((size_t)b*Cc*Tt + t)*Ff + f0;
    float sm = 0.f, sq = 0.f;
    #pragma unroll 8
    for (int i = 0; i < 32; i++) {
        int c = s + i*8;
        float v = xb[(size_t)c*Tt*Ff + f];
        tile[c][f] = v;
        sm += v; sq += v*v;
    }
    ps_[s][f] = sm; pq_[s][f] = sq;
    __syncthreads();
    if (tid < 32) {
        float S = 0.f, Q = 0.f;
        #pragma unroll
        for (int k = 0; k < 8; k++) { S += ps_[k][tid]; Q += pq_[k][tid]; }
        float mu = S * (1.0f/Cc);
        float var = Q * (1.0f/Cc) - mu*mu;
        smu[tid] = mu;
        srs[tid] = rsqrtf(var + 1e-5f);
    }
    __syncthreads();
    // write phase: i = f index, c = tid (coalesced in c)
    float gc = g[tid], bc = be[tid];
    #pragma unroll 8
    for (int i = 0; i < 32; i++) {
        float v = tile[tid][i];
        size_t o = ((size_t)bt*Ff + f0 + i)*Cc + tid;
        xs[o] = v;
        xn[o] = __float2bfloat16((v - smu[i]) * srs[i] * gc + bc);
    }
}

// ================= layernorm (256) -> bf16 =================
__global__ void k_ln(const float* __restrict__ in, __nv_bfloat16* __restrict__ outn,
                     const float* __restrict__ g, const float* __restrict__ be) {
    int row = blockIdx.x;
    int tid = threadIdx.x;
    float v = in[(size_t)row*Cc + tid];
    float s = v, q = v*v;
    #pragma unroll
    for (int o = 16; o; o >>= 1) {
        s += __shfl_xor_sync(0xffffffffu, s, o);
        q += __shfl_xor_sync(0xffffffffu, q, o);
    }
    __shared__ float ws[8], wq[8], mv[2];
    int w = tid >> 5, l = tid & 31;
    if (l == 0) { ws[w] = s; wq[w] = q; }
    __syncthreads();
    if (tid == 0) {
        float S = 0.f, Q = 0.f;
        #pragma unroll
        for (int i = 0; i < 8; i++) { S += ws[i]; Q += wq[i]; }
        float mu = S * (1.0f/Cc);
        float var = Q * (1.0f/Cc) - mu*mu;
        mv[0] = mu;
        mv[1] = rsqrtf(var + 1e-5f);
    }
    __syncthreads();
    outn[(size_t)row*Cc + tid] = __float2bfloat16((v - mv[0]) * mv[1] * g[tid] + be[tid]);
}

// ================= all weight transposes in one kernel =================
__global__ void k_wtall(const float* __restrict__ Wqkv, const float* __restrict__ Wproj,
                        const float* __restrict__ W1, const float* __restrict__ W2,
                        __nv_bfloat16* __restrict__ wqkvT, __nv_bfloat16* __restrict__ wprojT,
                        __nv_bfloat16* __restrict__ w1T, __nv_bfloat16* __restrict__ w2T) {
    int idx = blockIdx.x * 256 + threadIdx.x;
    if (idx < C3*Cc) {                                   // Wqkv: K=256, N=768
        int n = idx / Cc, k = idx - n*Cc;
        wqkvT[idx] = __float2bfloat16(Wqkv[(size_t)k*C3 + n]);
    } else if (idx < C3*Cc + Cc*Cc) {                    // Wproj: 256x256
        int j = idx - C3*Cc;
        int n = j / Cc, k = j - n*Cc;
        wprojT[j] = __float2bfloat16(Wproj[(size_t)k*Cc + n]);
    } else if (idx < C3*Cc + Cc*Cc + HIDN*Cc) {          // W1: K=256, N=512
        int j = idx - C3*Cc - Cc*Cc;
        int n = j / Cc, k = j - n*Cc;
        w1T[j] = __float2bfloat16(W1[(size_t)k*HIDN + n]);
    } else if (idx < C3*Cc + Cc*Cc + HIDN*Cc + Cc*HIDN) { // W2: K=512, N=256
        int j = idx - C3*Cc - Cc*Cc - HIDN*Cc;
        int n = j / HIDN, k = j - n*HIDN;
        w2T[j] = __float2bfloat16(W2[(size_t)k*Cc + n]);
    }
}

// ================= HMMA bf16 GEMM: C = A(M,K) @ Bt(N,K)^T =================
// CTA 128x128, 8 warps 2Mx4N, K chunks of 64, 3-stage cp.async ring (96KB dyn smem).
// OUT_MODE: 0 = fp32 row-major, 1 = bf16 row-major, 2 = fp32 scattered to (b,c,t,f)
#define GEMM_SMEM (6*128*64*2)   // 98304 B
template<int OUT_MODE, int HAS_BIAS, int GELU_F, int HAS_RES>
__global__ __launch_bounds__(256, 2)
void k_mmagemm(const __nv_bfloat16* __restrict__ A, const __nv_bfloat16* __restrict__ Bt,
               void* __restrict__ Co, const float* __restrict__ bias,
               const float* __restrict__ res, int N, int K) {
    extern __shared__ __nv_bfloat16 smg[];
    int tid = threadIdx.x, wid = tid >> 5, lid = tid & 31;
    int m0 = blockIdx.y * 128, n0 = blockIdx.x * 128;
    int wm = (wid & 1) * 64;
    int wn = (wid >> 1) * 32;

    int lrow = tid >> 3, lkb = tid & 7;
    uint32_t swoff = (lkb ^ (lrow & 7)) * 8;

    float c[4][4][4];
    #pragma unroll
    for (int mi = 0; mi < 4; mi++)
        #pragma unroll
        for (int ni = 0; ni < 4; ni++)
            #pragma unroll
            for (int j = 0; j < 4; j++) c[mi][ni][j] = 0.f;

    uint32_t sA0 = smem_u32(smg);                 // 3 x 16KB A stages
    uint32_t sB0 = sA0 + 3*16384;                 // 3 x 16KB B stages
    int nch = K >> 6;

    auto load_chunk = [&](int ck) {
        int k0 = ck << 6;
        uint32_t ab = sA0 + (ck % 3) * 16384;
        uint32_t bb = sB0 + (ck % 3) * 16384;
        const __nv_bfloat16* ga = A  + (size_t)(m0 + lrow)*K + k0 + lkb*8;
        const __nv_bfloat16* gb = Bt + (size_t)(n0 + lrow)*K + k0 + lkb*8;
        #pragma unroll
        for (int i = 0; i < 4; i++) {
            uint32_t d = ((lrow + i*32)*64 + swoff) * 2;
            cp16(ab + d, ga + (size_t)(i*32)*K);
            cp16(bb + d, gb + (size_t)(i*32)*K);
        }
        CP_COMMIT();
    };

    load_chunk(0);
    if (nch > 1) load_chunk(1);

    for (int cck = 0; cck < nch; cck++) {
        if (cck + 1 < nch) { CP_WAIT(1); } else { CP_WAIT(0); }
        __syncthreads();
        if (cck + 2 < nch) load_chunk(cck + 2);

        uint32_t sA = sA0 + (cck % 3) * 16384;
        uint32_t sB = sB0 + (cck % 3) * 16384;
        #pragma unroll
        for (int ks = 0; ks < 4; ks++) {
            uint32_t a[4][4], b[4][2];
            #pragma unroll
            for (int mi = 0; mi < 4; mi++) {
                int row = wm + mi*16 + (lid & 15);
                int kb  = ks*2 + (lid >> 4);
                uint32_t ad = sA + (row*64 + ((kb ^ (row & 7))*8))*2;
                ldsm4(a[mi][0], a[mi][1], a[mi][2], a[mi][3], ad);
            }
            #pragma unroll
            for (int nh = 0; nh < 2; nh++) {
                int nrow = wn + nh*16 + (lid & 7) + ((lid >> 4) << 3);
                int kb   = ks*2 + ((lid >> 3) & 1);
                uint32_t bd = sB + (nrow*64 + ((kb ^ (nrow & 7))*8))*2;
                uint32_t r0, r1, r2, r3;
                ldsm4(r0, r1, r2, r3, bd);
                b[nh*2+0][0] = r0; b[nh*2+0][1] = r1;
                b[nh*2+1][0] = r2; b[nh*2+1][1] = r3;
            }
            #pragma unroll
            for (int mi = 0; mi < 4; mi++)
                #pragma unroll
                for (int ni = 0; ni < 4; ni++)
                    mma16816(c[mi][ni], a[mi], b[ni]);
        }
        __syncthreads();
    }

    int qr = lid >> 2, qc = (lid & 3) * 2;
    #pragma unroll
    for (int mi = 0; mi < 4; mi++) {
        #pragma unroll
        for (int half = 0; half < 2; half++) {
            int m = m0 + wm + mi*16 + qr + half*8;
            #pragma unroll
            for (int ni = 0; ni < 4; ni++) {
                int n = n0 + wn + ni*8 + qc;
                float v0 = c[mi][ni][half*2+0];
                float v1 = c[mi][ni][half*2+1];
                if (HAS_BIAS) { v0 += bias[n]; v1 += bias[n+1]; }
                if (GELU_F) {
                    v0 = 0.5f*v0*(1.0f + erff(v0*0.7071067811865475f));
                    v1 = 0.5f*v1*(1.0f + erff(v1*0.7071067811865475f));
                }
                if (HAS_RES) {
                    float2 r2 = *(const float2*)&res[(size_t)m*N + n];
                    v0 += r2.x; v1 += r2.y;
                }
                if (OUT_MODE == 1) {
                    *(__nv_bfloat162*)((__nv_bfloat16*)Co + (size_t)m*N + n) =
                        __floats2bfloat162_rn(v0, v1);
                } else if (OUT_MODE == 0) {
                    *(float2*)((float*)Co + (size_t)m*N + n) = make_float2(v0, v1);
                } else {
                    // direct (b,c,t,f) store: m = bt*256 + f, n = channel
                    int bt2 = m >> 8, fF = m & 255;
                    int b2 = bt2 >> 6, t2 = bt2 & 63;
                    float* op = (float*)Co + ((size_t)(b2*Cc + n)*Tt + t2)*Ff + fF;
                    op[0] = v0;
                    op[(size_t)Tt*Ff] = v1;
                }
            }
        }
    }
}

// ================= attention via HMMA (conv3 fused), block per (bt,h) =================
#define ATTN_SMEM (3*256*40*2)   // 61440 B

__global__ __launch_bounds__(256, 1)
void k_attn(const __nv_bfloat16* __restrict__ qkvg, const float* __restrict__ dww,
            const float* __restrict__ temp, __nv_bfloat16* __restrict__ attn_out) {
    extern __shared__ __nv_bfloat16 smA[];
    __nv_bfloat16* Qs = smA;
    __nv_bfloat16* Ks = smA + 256*40;
    __nv_bfloat16* Vs = smA + 2*256*40;
    int bt = blockIdx.x, h = blockIdx.y;
    int tid = threadIdx.x, w = tid >> 5, l = tid & 31;
    const __nv_bfloat16* qkvb = qkvg + (size_t)bt*Ff*C3;
    float tp = temp[h];
    int chq = h*Dd + l, chk = Cc + chq, chv = 2*Cc + chq;
    float wq0 = dww[chq*3], wq1 = dww[chq*3+1], wq2 = dww[chq*3+2];
    float wk0 = dww[chk*3], wk1 = dww[chk*3+1], wk2 = dww[chk*3+2];
    float wv0 = dww[chv*3], wv1 = dww[chv*3+1], wv2 = dww[chv*3+2];

    for (int i = 0; i < 32; i++) {
        int j = w*32 + i;
        const __nv_bfloat16* r = qkvb + (size_t)j*C3;
        float qv = wq1*__bfloat162float(r[chq]);
        float kv = wk1*__bfloat162float(r[chk]);
        float vv = wv1*__bfloat162float(r[chv]);
        if (j > 0) {
            qv += wq0*__bfloat162float(r[chq - C3]);
            kv += wk0*__bfloat162float(r[chk - C3]);
            vv += wv0*__bfloat162float(r[chv - C3]);
        }
        if (j < Ff-1) {
            qv += wq2*__bfloat162float(r[chq + C3]);
            kv += wk2*__bfloat162float(r[chk + C3]);
            vv += wv2*__bfloat162float(r[chv + C3]);
        }
        float sq = qv*qv, sk = kv*kv;
        #pragma unroll
        for (int o = 16; o; o >>= 1) {
            sq += __shfl_xor_sync(0xffffffffu, sq, o);
            sk += __shfl_xor_sync(0xffffffffu, sk, o);
        }
        qv *= 1.f / fmaxf(sqrtf(sq), 1e-12f);
        kv *= 1.f / fmaxf(sqrtf(sk), 1e-12f);
        Qs[j*40 + l] = __float2bfloat16(qv);
        Ks[j*40 + l] = __float2bfloat16(kv);
        Vs[j*40 + l] = __float2bfloat16(vv);
    }
    __syncthreads();

    uint32_t sQ = smem_u32(Qs), sK = smem_u32(Ks), sV = smem_u32(Vs);
    int lid = l;
    int qr = lid >> 2;

    #pragma unroll
    for (int pass = 0; pass < 2; pass++) {
        int m0 = w*32 + pass*16;

        uint32_t a[2][4];
        #pragma unroll
        for (int ks = 0; ks < 2; ks++) {
            int row = m0 + (lid & 15);
            int kb  = ks*2 + (lid >> 4);
            ldsm4(a[ks][0], a[ks][1], a[ks][2], a[ks][3], sQ + (row*40 + kb*8)*2);
        }

        float s[32][4];
        #pragma unroll
        for (int nt = 0; nt < 32; nt++)
            #pragma unroll
            for (int j = 0; j < 4; j++) s[nt][j] = 0.f;
        #pragma unroll
        for (int ng = 0; ng < 16; ng++) {
            #pragma unroll
            for (int ks = 0; ks < 2; ks++) {
                int nrow = ng*16 + (lid & 7) + ((lid >> 4) << 3);
                int kb   = ks*2 + ((lid >> 3) & 1);
                uint32_t r0, r1, r2, r3;
                ldsm4(r0, r1, r2, r3, sK + (nrow*40 + kb*8)*2);
                uint32_t b0[2] = {r0, r1}, b1[2] = {r2, r3};
                mma16816(s[ng*2],   a[ks], b0);
                mma16816(s[ng*2+1], a[ks], b1);
            }
        }

        float mlo = -1e30f, mhi = -1e30f;
        #pragma unroll
        for (int nt = 0; nt < 32; nt++) {
            #pragma unroll
            for (int j = 0; j < 4; j++) s[nt][j] *= tp;
            mlo = fmaxf(mlo, fmaxf(s[nt][0], s[nt][1]));
            mhi = fmaxf(mhi, fmaxf(s[nt][2], s[nt][3]));
        }
        #pragma unroll
        for (int o = 1; o <= 2; o <<= 1) {
            mlo = fmaxf(mlo, __shfl_xor_sync(0xffffffffu, mlo, o));
            mhi = fmaxf(mhi, __shfl_xor_sync(0xffffffffu, mhi, o));
        }
        float zlo = 0.f, zhi = 0.f;
        #pragma unroll
        for (int nt = 0; nt < 32; nt++) {
            s[nt][0] = __expf(s[nt][0] - mlo);
            s[nt][1] = __expf(s[nt][1] - mlo);
            s[nt][2] = __expf(s[nt][2] - mhi);
            s[nt][3] = __expf(s[nt][3] - mhi);
            zlo += s[nt][0] + s[nt][1];
            zhi += s[nt][2] + s[nt][3];
        }
        #pragma unroll
        for (int o = 1; o <= 2; o <<= 1) {
            zlo += __shfl_xor_sync(0xffffffffu, zlo, o);
            zhi += __shfl_xor_sync(0xffffffffu, zhi, o);
        }

        float ov[4][4];
        #pragma unroll
        for (int nt = 0; nt < 4; nt++)
            #pragma unroll
            for (int j = 0; j < 4; j++) ov[nt][j] = 0.f;
        #pragma unroll
        for (int kk = 0; kk < 16; kk++) {
            uint32_t pa[4];
            {
                __nv_bfloat162 t0 = __floats2bfloat162_rn(s[2*kk][0],   s[2*kk][1]);
                __nv_bfloat162 t1 = __floats2bfloat162_rn(s[2*kk][2],   s[2*kk][3]);
                __nv_bfloat162 t2 = __floats2bfloat162_rn(s[2*kk+1][0], s[2*kk+1][1]);
                __nv_bfloat162 t3 = __floats2bfloat162_rn(s[2*kk+1][2], s[2*kk+1][3]);
                pa[0] = *(uint32_t*)&t0; pa[1] = *(uint32_t*)&t1;
                pa[2] = *(uint32_t*)&t2; pa[3] = *(uint32_t*)&t3;
            }
            int vrow = kk*16 + (lid & 15);
            #pragma unroll
            for (int half = 0; half < 2; half++) {
                uint32_t r0, r1, r2, r3;
                ldsm4t(r0, r1, r2, r3, sV + (vrow*40)*2 + (lid >> 4)*16 + half*32);
                uint32_t b0[2] = {r0, r1}, b1[2] = {r2, r3};
                mma16816(ov[half*2+0], pa, b0);
                mma16816(ov[half*2+1], pa, b1);
            }
        }

        float ilo = 1.f/zlo, ihi = 1.f/zhi;
        #pragma unroll
        for (int nt = 0; nt < 4; nt++) {
            int col = h*Dd + nt*8 + (lid & 3)*2;
            int flo = m0 + qr, fhi = m0 + qr + 8;
            *(__nv_bfloat162*)&attn_out[((size_t)bt*Ff + flo)*Cc + col] =
                __floats2bfloat162_rn(ov[nt][0]*ilo, ov[nt][1]*ilo);
            *(__nv_bfloat162*)&attn_out[((size_t)bt*Ff + fhi)*Cc + col] =
                __floats2bfloat162_rn(ov[nt][2]*ihi, ov[nt][3]*ihi);
        }
    }
}

// ================= launch =================
extern "C" void kernel_launch(void* const* d_in, const int* in_sizes, int n_in,
                              void* d_out, int out_size) {
    const float *x, *n1g, *n1b, *Wqkv, *dww, *Wproj, *temp, *n2g, *n2b, *W1, *b1, *W2, *b2;
    const int X_SIZE = Bb*Cc*Tt*Ff;
    if (n_in >= 13 && in_sizes[0] == X_SIZE) {
        x     = (const float*)d_in[0];  n1g   = (const float*)d_in[1];
        n1b   = (const float*)d_in[2];  Wqkv  = (const float*)d_in[3];
        dww   = (const float*)d_in[4];  Wproj = (const float*)d_in[5];
        temp  = (const float*)d_in[6];  n2g   = (const float*)d_in[7];
        n2b   = (const float*)d_in[8];  W1    = (const float*)d_in[9];
        b1    = (const float*)d_in[10]; W2    = (const float*)d_in[11];
        b2    = (const float*)d_in[12];
    } else {
        W1    = (const float*)d_in[0];  W2    = (const float*)d_in[1];
        Wproj = (const float*)d_in[2];  Wqkv  = (const float*)d_in[3];
        b1    = (const float*)d_in[4];  b2    = (const float*)d_in[5];
        dww   = (const float*)d_in[6];  n1b   = (const float*)d_in[7];
        n1g   = (const float*)d_in[8];  n2b   = (const float*)d_in[9];
        n2g   = (const float*)d_in[10]; temp  = (const float*)d_in[11];
        x     = (const float*)d_in[12];
    }

    void *vp;
    float *xs, *out1;
    __nv_bfloat16 *xn, *att, *qkv, *wqkvT, *wprojT, *w1T, *w2T;
    cudaGetSymbolAddress(&vp, g_xs);     xs     = (float*)vp;
    cudaGetSymbolAddress(&vp, g_out1);   out1   = (float*)vp;
    cudaGetSymbolAddress(&vp, g_xn);     xn     = (__nv_bfloat16*)vp;
    cudaGetSymbolAddress(&vp, g_att);    att    = (__nv_bfloat16*)vp;
    cudaGetSymbolAddress(&vp, g_qkv);    qkv    = (__nv_bfloat16*)vp;
    cudaGetSymbolAddress(&vp, g_wqkvT);  wqkvT  = (__nv_bfloat16*)vp;
    cudaGetSymbolAddress(&vp, g_wprojT); wprojT = (__nv_bfloat16*)vp;
    cudaGetSymbolAddress(&vp, g_w1T);    w1T    = (__nv_bfloat16*)vp;
    cudaGetSymbolAddress(&vp, g_w2T);    w2T    = (__nv_bfloat16*)vp;
    __nv_bfloat16* hid = qkv;   // qkv dead after attention; reuse for MLP hidden

    cudaFuncSetAttribute(k_attn, cudaFuncAttributeMaxDynamicSharedMemorySize, ATTN_SMEM);
    cudaFuncSetAttribute(k_mmagemm<1,0,0,0>, cudaFuncAttributeMaxDynamicSharedMemorySize, GEMM_SMEM);
    cudaFuncSetAttribute(k_mmagemm<0,0,0,1>, cudaFuncAttributeMaxDynamicSharedMemorySize, GEMM_SMEM);
    cudaFuncSetAttribute(k_mmagemm<1,1,1,0>, cudaFuncAttributeMaxDynamicSharedMemorySize, GEMM_SMEM);
    cudaFuncSetAttribute(k_mmagemm<2,1,0,1>, cudaFuncAttributeMaxDynamicSharedMemorySize, GEMM_SMEM);

    // all weight transposes, one launch
    k_wtall<<<(C3*Cc + Cc*Cc + HIDN*Cc + Cc*HIDN + 255)/256, 256>>>(
        Wqkv, Wproj, W1, W2, wqkvT, wprojT, w1T, w2T);
    // fused transpose-in + LN1
    k_in<<<dim3(Ff/32, BT), 256>>>(x, xs, xn, n1g, n1b);
    // QKV gemm
    k_mmagemm<1,0,0,0><<<dim3(C3/128, ROWS/128), 256, GEMM_SMEM>>>(xn, wqkvT, qkv, nullptr, nullptr, C3, Cc);
    // attention (conv fused)
    k_attn<<<dim3(BT, Hh), 256, ATTN_SMEM>>>(qkv, dww, temp, att);
    // proj + residual(xs)
    k_mmagemm<0,0,0,1><<<dim3(Cc/128, ROWS/128), 256, GEMM_SMEM>>>(att, wprojT, out1, nullptr, xs, Cc, Cc);
    // LN2
    k_ln<<<ROWS, 256>>>(out1, xn, n2g, n2b);
    // MLP1 + bias + gelu
    k_mmagemm<1,1,1,0><<<dim3(HIDN/128, ROWS/128), 256, GEMM_SMEM>>>(xn, w1T, hid, b1, nullptr, HIDN, Cc);
    // MLP2 + bias + residual(out1), writing DIRECTLY to d_out in (b,c,t,f)
    k_mmagemm<2,1,0,1><<<dim3(Cc/128, ROWS/128), 256, GEMM_SMEM>>>(hid, w2T, d_out, b2, out1, Cc, HIDN);
}

// round 11
// speedup vs baseline: 4.7829x; 1.2587x over previous
#include <cuda_runtime.h>
#include <cuda_bf16.h>
#include <math.h>
#include <stdint.h>

#define Bb 4
#define Tt 64
#define Cc 256
#define Ff 256
#define Hh 8
#define Dd 32
#define HIDN 512
#define BT (Bb*Tt)            // 256
#define ROWS (BT*Ff)          // 65536
#define C3 (3*Cc)             // 768

// ---------------- scratch (device globals; resolved via cudaGetSymbolAddress) ----
__device__ float          g_xs  [ROWS*Cc];    // residual fp32 (raw transposed x)
__device__ float          g_out1[ROWS*Cc];    // after proj + residual
__device__ __nv_bfloat16  g_xn  [ROWS*Cc];    // LN out (bf16)
__device__ __nv_bfloat16  g_att [ROWS*Cc];    // attention out (bf16)
__device__ __nv_bfloat16  g_qkv [ROWS*C3];    // qkv bf16; reused as MLP hidden
__device__ __nv_bfloat16  g_wqkvT [C3*Cc];    // transposed bf16 weights [N][K]
__device__ __nv_bfloat16  g_wprojT[Cc*Cc];
__device__ __nv_bfloat16  g_w1T   [HIDN*Cc];
__device__ __nv_bfloat16  g_w2T   [Cc*HIDN];

__device__ __forceinline__ uint32_t smem_u32(const void* p) {
    uint32_t a;
    asm("{ .reg .u64 t; cvta.to.shared.u64 t, %1; cvt.u32.u64 %0, t; }" : "=r"(a) : "l"(p));
    return a;
}
__device__ __forceinline__ void ldsm4(uint32_t& r0, uint32_t& r1, uint32_t& r2, uint32_t& r3,
                                      uint32_t addr) {
    asm volatile("ldmatrix.sync.aligned.m8n8.x4.shared.b16 {%0,%1,%2,%3}, [%4];"
                 : "=r"(r0), "=r"(r1), "=r"(r2), "=r"(r3) : "r"(addr));
}
__device__ __forceinline__ void ldsm4t(uint32_t& r0, uint32_t& r1, uint32_t& r2, uint32_t& r3,
                                       uint32_t addr) {
    asm volatile("ldmatrix.sync.aligned.m8n8.x4.trans.shared.b16 {%0,%1,%2,%3}, [%4];"
                 : "=r"(r0), "=r"(r1), "=r"(r2), "=r"(r3) : "r"(addr));
}
__device__ __forceinline__ void mma16816(float* c, const uint32_t* a, const uint32_t* b) {
    asm volatile(
        "mma.sync.aligned.m16n8k16.row.col.f32.bf16.bf16.f32 "
        "{%0,%1,%2,%3}, {%4,%5,%6,%7}, {%8,%9}, {%0,%1,%2,%3};"
        : "+f"(c[0]), "+f"(c[1]), "+f"(c[2]), "+f"(c[3])
        : "r"(a[0]), "r"(a[1]), "r"(a[2]), "r"(a[3]), "r"(b[0]), "r"(b[1]));
}
__device__ __forceinline__ void cp16(uint32_t sdst, const void* gsrc) {
    asm volatile("cp.async.cg.shared.global [%0], [%1], 16;" :: "r"(sdst), "l"(gsrc));
}
#define CP_COMMIT() asm volatile("cp.async.commit_group;" ::: "memory")
#define CP_WAIT(n)  asm volatile("cp.async.wait_group %0;" :: "n"(n) : "memory")

// ================= fused input: transpose x(b,c,t,f)->(bt,f,c) + LN1 =================
__global__ __launch_bounds__(256)
void k_in(const float* __restrict__ x, float* __restrict__ xs,
          __nv_bfloat16* __restrict__ xn,
          const float* __restrict__ g, const float* __restrict__ be) {
    __shared__ float tile[256][33];
    __shared__ float ps_[8][32], pq_[8][32];
    __shared__ float smu[32], srs[32];
    int bt = blockIdx.y, f0 = blockIdx.x * 32;
    int b = bt >> 6, t = bt & 63;
    int tid = threadIdx.x;
    int f = tid & 31, s = tid >> 5;

    const float* xb = x + ((size_t)b*Cc*Tt + t)*Ff + f0;
    float sm = 0.f, sq = 0.f;
    #pragma unroll 8
    for (int i = 0; i < 32; i++) {
        int c = s + i*8;
        float v = xb[(size_t)c*Tt*Ff + f];
        tile[c][f] = v;
        sm += v; sq += v*v;
    }
    ps_[s][f] = sm; pq_[s][f] = sq;
    __syncthreads();
    if (tid < 32) {
        float S = 0.f, Q = 0.f;
        #pragma unroll
        for (int k = 0; k < 8; k++) { S += ps_[k][tid]; Q += pq_[k][tid]; }
        float mu = S * (1.0f/Cc);
        float var = Q * (1.0f/Cc) - mu*mu;
        smu[tid] = mu;
        srs[tid] = rsqrtf(var + 1e-5f);
    }
    __syncthreads();
    float gc = g[tid], bc = be[tid];
    #pragma unroll 8
    for (int i = 0; i < 32; i++) {
        float v = tile[tid][i];
        size_t o = ((size_t)bt*Ff + f0 + i)*Cc + tid;
        xs[o] = v;
        xn[o] = __float2bfloat16((v - smu[i]) * srs[i] * gc + bc);
    }
}

// ================= layernorm (256) -> bf16 =================
__global__ void k_ln(const float* __restrict__ in, __nv_bfloat16* __restrict__ outn,
                     const float* __restrict__ g, const float* __restrict__ be) {
    int row = blockIdx.x;
    int tid = threadIdx.x;
    float v = in[(size_t)row*Cc + tid];
    float s = v, q = v*v;
    #pragma unroll
    for (int o = 16; o; o >>= 1) {
        s += __shfl_xor_sync(0xffffffffu, s, o);
        q += __shfl_xor_sync(0xffffffffu, q, o);
    }
    __shared__ float ws[8], wq[8], mv[2];
    int w = tid >> 5, l = tid & 31;
    if (l == 0) { ws[w] = s; wq[w] = q; }
    __syncthreads();
    if (tid == 0) {
        float S = 0.f, Q = 0.f;
        #pragma unroll
        for (int i = 0; i < 8; i++) { S += ws[i]; Q += wq[i]; }
        float mu = S * (1.0f/Cc);
        float var = Q * (1.0f/Cc) - mu*mu;
        mv[0] = mu;
        mv[1] = rsqrtf(var + 1e-5f);
    }
    __syncthreads();
    outn[(size_t)row*Cc + tid] = __float2bfloat16((v - mv[0]) * mv[1] * g[tid] + be[tid]);
}

// ================= all weight transposes in one kernel =================
__global__ void k_wtall(const float* __restrict__ Wqkv, const float* __restrict__ Wproj,
                        const float* __restrict__ W1, const float* __restrict__ W2,
                        __nv_bfloat16* __restrict__ wqkvT, __nv_bfloat16* __restrict__ wprojT,
                        __nv_bfloat16* __restrict__ w1T, __nv_bfloat16* __restrict__ w2T) {
    int idx = blockIdx.x * 256 + threadIdx.x;
    if (idx < C3*Cc) {
        int n = idx / Cc, k = idx - n*Cc;
        wqkvT[idx] = __float2bfloat16(Wqkv[(size_t)k*C3 + n]);
    } else if (idx < C3*Cc + Cc*Cc) {
        int j = idx - C3*Cc;
        int n = j / Cc, k = j - n*Cc;
        wprojT[j] = __float2bfloat16(Wproj[(size_t)k*Cc + n]);
    } else if (idx < C3*Cc + Cc*Cc + HIDN*Cc) {
        int j = idx - C3*Cc - Cc*Cc;
        int n = j / Cc, k = j - n*Cc;
        w1T[j] = __float2bfloat16(W1[(size_t)k*HIDN + n]);
    } else if (idx < C3*Cc + Cc*Cc + HIDN*Cc + Cc*HIDN) {
        int j = idx - C3*Cc - Cc*Cc - HIDN*Cc;
        int n = j / HIDN, k = j - n*HIDN;
        w2T[j] = __float2bfloat16(W2[(size_t)k*Cc + n]);
    }
}

// ================= HMMA bf16 GEMM: C = A(M,K) @ Bt(N,K)^T =================
#define GEMM_SMEM (6*128*64*2)   // 98304 B
template<int OUT_MODE, int HAS_BIAS, int GELU_F, int HAS_RES>
__global__ __launch_bounds__(256, 2)
void k_mmagemm(const __nv_bfloat16* __restrict__ A, const __nv_bfloat16* __restrict__ Bt,
               void* __restrict__ Co, const float* __restrict__ bias,
               const float* __restrict__ res, int N, int K) {
    extern __shared__ __nv_bfloat16 smg[];
    int tid = threadIdx.x, wid = tid >> 5, lid = tid & 31;
    int m0 = blockIdx.y * 128, n0 = blockIdx.x * 128;
    int wm = (wid & 1) * 64;
    int wn = (wid >> 1) * 32;

    int lrow = tid >> 3, lkb = tid & 7;
    uint32_t swoff = (lkb ^ (lrow & 7)) * 8;

    float c[4][4][4];
    #pragma unroll
    for (int mi = 0; mi < 4; mi++)
        #pragma unroll
        for (int ni = 0; ni < 4; ni++)
            #pragma unroll
            for (int j = 0; j < 4; j++) c[mi][ni][j] = 0.f;

    uint32_t sA0 = smem_u32(smg);
    uint32_t sB0 = sA0 + 3*16384;
    int nch = K >> 6;

    auto load_chunk = [&](int ck) {
        int k0 = ck << 6;
        uint32_t ab = sA0 + (ck % 3) * 16384;
        uint32_t bb = sB0 + (ck % 3) * 16384;
        const __nv_bfloat16* ga = A  + (size_t)(m0 + lrow)*K + k0 + lkb*8;
        const __nv_bfloat16* gb = Bt + (size_t)(n0 + lrow)*K + k0 + lkb*8;
        #pragma unroll
        for (int i = 0; i < 4; i++) {
            uint32_t d = ((lrow + i*32)*64 + swoff) * 2;
            cp16(ab + d, ga + (size_t)(i*32)*K);
            cp16(bb + d, gb + (size_t)(i*32)*K);
        }
        CP_COMMIT();
    };

    load_chunk(0);
    if (nch > 1) load_chunk(1);

    for (int cck = 0; cck < nch; cck++) {
        if (cck + 1 < nch) { CP_WAIT(1); } else { CP_WAIT(0); }
        __syncthreads();
        if (cck + 2 < nch) load_chunk(cck + 2);

        uint32_t sA = sA0 + (cck % 3) * 16384;
        uint32_t sB = sB0 + (cck % 3) * 16384;
        #pragma unroll
        for (int ks = 0; ks < 4; ks++) {
            uint32_t a[4][4], b[4][2];
            #pragma unroll
            for (int mi = 0; mi < 4; mi++) {
                int row = wm + mi*16 + (lid & 15);
                int kb  = ks*2 + (lid >> 4);
                uint32_t ad = sA + (row*64 + ((kb ^ (row & 7))*8))*2;
                ldsm4(a[mi][0], a[mi][1], a[mi][2], a[mi][3], ad);
            }
            #pragma unroll
            for (int nh = 0; nh < 2; nh++) {
                int nrow = wn + nh*16 + (lid & 7) + ((lid >> 4) << 3);
                int kb   = ks*2 + ((lid >> 3) & 1);
                uint32_t bd = sB + (nrow*64 + ((kb ^ (nrow & 7))*8))*2;
                uint32_t r0, r1, r2, r3;
                ldsm4(r0, r1, r2, r3, bd);
                b[nh*2+0][0] = r0; b[nh*2+0][1] = r1;
                b[nh*2+1][0] = r2; b[nh*2+1][1] = r3;
            }
            #pragma unroll
            for (int mi = 0; mi < 4; mi++)
                #pragma unroll
                for (int ni = 0; ni < 4; ni++)
                    mma16816(c[mi][ni], a[mi], b[ni]);
        }
        __syncthreads();
    }

    int qr = lid >> 2, qc = (lid & 3) * 2;
    #pragma unroll
    for (int mi = 0; mi < 4; mi++) {
        #pragma unroll
        for (int half = 0; half < 2; half++) {
            int m = m0 + wm + mi*16 + qr + half*8;
            #pragma unroll
            for (int ni = 0; ni < 4; ni++) {
                int n = n0 + wn + ni*8 + qc;
                float v0 = c[mi][ni][half*2+0];
                float v1 = c[mi][ni][half*2+1];
                if (HAS_BIAS) { v0 += bias[n]; v1 += bias[n+1]; }
                if (GELU_F) {
                    v0 = 0.5f*v0*(1.0f + erff(v0*0.7071067811865475f));
                    v1 = 0.5f*v1*(1.0f + erff(v1*0.7071067811865475f));
                }
                if (HAS_RES) {
                    float2 r2 = *(const float2*)&res[(size_t)m*N + n];
                    v0 += r2.x; v1 += r2.y;
                }
                if (OUT_MODE == 1) {
                    *(__nv_bfloat162*)((__nv_bfloat16*)Co + (size_t)m*N + n) =
                        __floats2bfloat162_rn(v0, v1);
                } else if (OUT_MODE == 0) {
                    *(float2*)((float*)Co + (size_t)m*N + n) = make_float2(v0, v1);
                } else {
                    int bt2 = m >> 8, fF = m & 255;
                    int b2 = bt2 >> 6, t2 = bt2 & 63;
                    float* op = (float*)Co + ((size_t)(b2*Cc + n)*Tt + t2)*Ff + fF;
                    op[0] = v0;
                    op[(size_t)Tt*Ff] = v1;
                }
            }
        }
    }
}

// ================= attention via HMMA (conv3 fused), block per (bt,h) =================
// Q/K l2-normalized => |score| <= |temp|: softmax max-shift is unnecessary.
// Keys streamed in 4 chunks of 64 -> S fragment live range is 32 regs, not 128.
#define ATTN_SMEM (3*256*40*2)   // 61440 B

__global__ __launch_bounds__(256, 2)
void k_attn(const __nv_bfloat16* __restrict__ qkvg, const float* __restrict__ dww,
            const float* __restrict__ temp, __nv_bfloat16* __restrict__ attn_out) {
    extern __shared__ __nv_bfloat16 smA[];
    __nv_bfloat16* Qs = smA;
    __nv_bfloat16* Ks = smA + 256*40;
    __nv_bfloat16* Vs = smA + 2*256*40;
    int bt = blockIdx.x, h = blockIdx.y;
    int tid = threadIdx.x, w = tid >> 5, l = tid & 31;
    const __nv_bfloat16* qkvb = qkvg + (size_t)bt*Ff*C3;
    float tp = temp[h];
    int chq = h*Dd + l, chk = Cc + chq, chv = 2*Cc + chq;
    float wq0 = dww[chq*3], wq1 = dww[chq*3+1], wq2 = dww[chq*3+2];
    float wk0 = dww[chk*3], wk1 = dww[chk*3+1], wk2 = dww[chk*3+2];
    float wv0 = dww[chv*3], wv1 = dww[chv*3+1], wv2 = dww[chv*3+2];

    for (int i = 0; i < 32; i++) {
        int j = w*32 + i;
        const __nv_bfloat16* r = qkvb + (size_t)j*C3;
        float qv = wq1*__bfloat162float(r[chq]);
        float kv = wk1*__bfloat162float(r[chk]);
        float vv = wv1*__bfloat162float(r[chv]);
        if (j > 0) {
            qv += wq0*__bfloat162float(r[chq - C3]);
            kv += wk0*__bfloat162float(r[chk - C3]);
            vv += wv0*__bfloat162float(r[chv - C3]);
        }
        if (j < Ff-1) {
            qv += wq2*__bfloat162float(r[chq + C3]);
            kv += wk2*__bfloat162float(r[chk + C3]);
            vv += wv2*__bfloat162float(r[chv + C3]);
        }
        float sq = qv*qv, sk = kv*kv;
        #pragma unroll
        for (int o = 16; o; o >>= 1) {
            sq += __shfl_xor_sync(0xffffffffu, sq, o);
            sk += __shfl_xor_sync(0xffffffffu, sk, o);
        }
        qv *= 1.f / fmaxf(sqrtf(sq), 1e-12f);
        kv *= 1.f / fmaxf(sqrtf(sk), 1e-12f);
        Qs[j*40 + l] = __float2bfloat16(qv);
        Ks[j*40 + l] = __float2bfloat16(kv);
        Vs[j*40 + l] = __float2bfloat16(vv);
    }
    __syncthreads();

    uint32_t sQ = smem_u32(Qs), sK = smem_u32(Ks), sV = smem_u32(Vs);
    int lid = l;
    int qr = lid >> 2;

    #pragma unroll
    for (int pass = 0; pass < 2; pass++) {
        int m0 = w*32 + pass*16;

        uint32_t a[2][4];
        #pragma unroll
        for (int ks = 0; ks < 2; ks++) {
            int row = m0 + (lid & 15);
            int kb  = ks*2 + (lid >> 4);
            ldsm4(a[ks][0], a[ks][1], a[ks][2], a[ks][3], sQ + (row*40 + kb*8)*2);
        }

        float ov[4][4];
        #pragma unroll
        for (int nt = 0; nt < 4; nt++)
            #pragma unroll
            for (int j = 0; j < 4; j++) ov[nt][j] = 0.f;
        float zlo = 0.f, zhi = 0.f;

        #pragma unroll
        for (int ch = 0; ch < 4; ch++) {            // 64 keys per chunk
            float s[8][4];
            #pragma unroll
            for (int nt = 0; nt < 8; nt++)
                #pragma unroll
                for (int j = 0; j < 4; j++) s[nt][j] = 0.f;
            #pragma unroll
            for (int g = 0; g < 4; g++) {           // 16-key groups
                #pragma unroll
                for (int ks = 0; ks < 2; ks++) {
                    int nrow = ch*64 + g*16 + (lid & 7) + ((lid >> 4) << 3);
                    int kb   = ks*2 + ((lid >> 3) & 1);
                    uint32_t r0, r1, r2, r3;
                    ldsm4(r0, r1, r2, r3, sK + (nrow*40 + kb*8)*2);
                    uint32_t b0[2] = {r0, r1}, b1[2] = {r2, r3};
                    mma16816(s[g*2],   a[ks], b0);
                    mma16816(s[g*2+1], a[ks], b1);
                }
            }
            // exp (no max shift needed: |s*tp| <= |tp|), accumulate z
            #pragma unroll
            for (int nt = 0; nt < 8; nt++) {
                s[nt][0] = __expf(s[nt][0]*tp);
                s[nt][1] = __expf(s[nt][1]*tp);
                s[nt][2] = __expf(s[nt][2]*tp);
                s[nt][3] = __expf(s[nt][3]*tp);
                zlo += s[nt][0] + s[nt][1];
                zhi += s[nt][2] + s[nt][3];
            }
            // PV for this chunk
            #pragma unroll
            for (int kk = 0; kk < 4; kk++) {
                uint32_t pa[4];
                {
                    __nv_bfloat162 t0 = __floats2bfloat162_rn(s[2*kk][0],   s[2*kk][1]);
                    __nv_bfloat162 t1 = __floats2bfloat162_rn(s[2*kk][2],   s[2*kk][3]);
                    __nv_bfloat162 t2 = __floats2bfloat162_rn(s[2*kk+1][0], s[2*kk+1][1]);
                    __nv_bfloat162 t3 = __floats2bfloat162_rn(s[2*kk+1][2], s[2*kk+1][3]);
                    pa[0] = *(uint32_t*)&t0; pa[1] = *(uint32_t*)&t1;
                    pa[2] = *(uint32_t*)&t2; pa[3] = *(uint32_t*)&t3;
                }
                int vrow = ch*64 + kk*16 + (lid & 15);
                #pragma unroll
                for (int half = 0; half < 2; half++) {
                    uint32_t r0, r1, r2, r3;
                    ldsm4t(r0, r1, r2, r3, sV + (vrow*40)*2 + (lid >> 4)*16 + half*32);
                    uint32_t b0[2] = {r0, r1}, b1[2] = {r2, r3};
                    mma16816(ov[half*2+0], pa, b0);
                    mma16816(ov[half*2+1], pa, b1);
                }
            }
        }

        #pragma unroll
        for (int o = 1; o <= 2; o <<= 1) {
            zlo += __shfl_xor_sync(0xffffffffu, zlo, o);
            zhi += __shfl_xor_sync(0xffffffffu, zhi, o);
        }
        float ilo = 1.f/zlo, ihi = 1.f/zhi;
        #pragma unroll
        for (int nt = 0; nt < 4; nt++) {
            int col = h*Dd + nt*8 + (lid & 3)*2;
            int flo = m0 + qr, fhi = m0 + qr + 8;
            *(__nv_bfloat162*)&attn_out[((size_t)bt*Ff + flo)*Cc + col] =
                __floats2bfloat162_rn(ov[nt][0]*ilo, ov[nt][1]*ilo);
            *(__nv_bfloat162*)&attn_out[((size_t)bt*Ff + fhi)*Cc + col] =
                __floats2bfloat162_rn(ov[nt][2]*ihi, ov[nt][3]*ihi);
        }
    }
}

// ================= launch =================
extern "C" void kernel_launch(void* const* d_in, const int* in_sizes, int n_in,
                              void* d_out, int out_size) {
    const float *x, *n1g, *n1b, *Wqkv, *dww, *Wproj, *temp, *n2g, *n2b, *W1, *b1, *W2, *b2;
    const int X_SIZE = Bb*Cc*Tt*Ff;
    if (n_in >= 13 && in_sizes[0] == X_SIZE) {
        x     = (const float*)d_in[0];  n1g   = (const float*)d_in[1];
        n1b   = (const float*)d_in[2];  Wqkv  = (const float*)d_in[3];
        dww   = (const float*)d_in[4];  Wproj = (const float*)d_in[5];
        temp  = (const float*)d_in[6];  n2g   = (const float*)d_in[7];
        n2b   = (const float*)d_in[8];  W1    = (const float*)d_in[9];
        b1    = (const float*)d_in[10]; W2    = (const float*)d_in[11];
        b2    = (const float*)d_in[12];
    } else {
        W1    = (const float*)d_in[0];  W2    = (const float*)d_in[1];
        Wproj = (const float*)d_in[2];  Wqkv  = (const float*)d_in[3];
        b1    = (const float*)d_in[4];  b2    = (const float*)d_in[5];
        dww   = (const float*)d_in[6];  n1b   = (const float*)d_in[7];
        n1g   = (const float*)d_in[8];  n2b   = (const float*)d_in[9];
        n2g   = (const float*)d_in[10]; temp  = (const float*)d_in[11];
        x     = (const float*)d_in[12];
    }

    void *vp;
    float *xs, *out1;
    __nv_bfloat16 *xn, *att, *qkv, *wqkvT, *wprojT, *w1T, *w2T;
    cudaGetSymbolAddress(&vp, g_xs);     xs     = (float*)vp;
    cudaGetSymbolAddress(&vp, g_out1);   out1   = (float*)vp;
    cudaGetSymbolAddress(&vp, g_xn);     xn     = (__nv_bfloat16*)vp;
    cudaGetSymbolAddress(&vp, g_att);    att    = (__nv_bfloat16*)vp;
    cudaGetSymbolAddress(&vp, g_qkv);    qkv    = (__nv_bfloat16*)vp;
    cudaGetSymbolAddress(&vp, g_wqkvT);  wqkvT  = (__nv_bfloat16*)vp;
    cudaGetSymbolAddress(&vp, g_wprojT); wprojT = (__nv_bfloat16*)vp;
    cudaGetSymbolAddress(&vp, g_w1T);    w1T    = (__nv_bfloat16*)vp;
    cudaGetSymbolAddress(&vp, g_w2T);    w2T    = (__nv_bfloat16*)vp;
    __nv_bfloat16* hid = qkv;

    cudaFuncSetAttribute(k_attn, cudaFuncAttributeMaxDynamicSharedMemorySize, ATTN_SMEM);
    cudaFuncSetAttribute(k_mmagemm<1,0,0,0>, cudaFuncAttributeMaxDynamicSharedMemorySize, GEMM_SMEM);
    cudaFuncSetAttribute(k_mmagemm<0,0,0,1>, cudaFuncAttributeMaxDynamicSharedMemorySize, GEMM_SMEM);
    cudaFuncSetAttribute(k_mmagemm<1,1,1,0>, cudaFuncAttributeMaxDynamicSharedMemorySize, GEMM_SMEM);
    cudaFuncSetAttribute(k_mmagemm<2,1,0,1>, cudaFuncAttributeMaxDynamicSharedMemorySize, GEMM_SMEM);

    k_wtall<<<(C3*Cc + Cc*Cc + HIDN*Cc + Cc*HIDN + 255)/256, 256>>>(
        Wqkv, Wproj, W1, W2, wqkvT, wprojT, w1T, w2T);
    k_in<<<dim3(Ff/32, BT), 256>>>(x, xs, xn, n1g, n1b);
    k_mmagemm<1,0,0,0><<<dim3(C3/128, ROWS/128), 256, GEMM_SMEM>>>(xn, wqkvT, qkv, nullptr, nullptr, C3, Cc);
    k_attn<<<dim3(BT, Hh), 256, ATTN_SMEM>>>(qkv, dww, temp, att);
    k_mmagemm<0,0,0,1><<<dim3(Cc/128, ROWS/128), 256, GEMM_SMEM>>>(att, wprojT, out1, nullptr, xs, Cc, Cc);
    k_ln<<<ROWS, 256>>>(out1, xn, n2g, n2b);
    k_mmagemm<1,1,1,0><<<dim3(HIDN/128, ROWS/128), 256, GEMM_SMEM>>>(xn, w1T, hid, b1, nullptr, HIDN, Cc);
    k_mmagemm<2,1,0,1><<<dim3(Cc/128, ROWS/128), 256, GEMM_SMEM>>>(hid, w2T, d_out, b2, out1, Cc, HIDN);
}